// round 5
// baseline (speedup 1.0000x reference)
#include <cuda_runtime.h>
#include <cuda_bf16.h>

#define NN 50000        // capacity: nodes
#define EE 800000       // capacity: edges
#define HID 128

// ---------------- scratch (static __device__, no allocation) ----------------
__device__ float g_h[NN * 128];
__device__ float g_h2[NN * 128];
__device__ float g_agg[NN * 128];
__device__ int   g_deg[NN];
__device__ int   g_off[NN + 1];
__device__ int   g_cur[NN];
__device__ int   g_csr[EE];
__device__ float g_WT1[256 * 128];
__device__ float g_WT2[256 * 128];
__device__ int   g_E;        // true edge count (device-detected)
__device__ int   g_e64;      // edge_index is int64
__device__ int   g_x64;      // x is int64

// ---------------- dtype / count detection ----------------
__global__ void detect_kernel(const int* __restrict__ ei, long long eiW,
                              const int* __restrict__ x, long long xW,
                              int elemMode) {
    if (blockIdx.x == 0 && threadIdx.x == 0) {
        int e64 = 1;
        for (long long i = 1; i < 256 && i < eiW; i += 2)
            if (ei[i] != 0) { e64 = 0; break; }
        int x64 = 1;
        for (long long i = 1; i < 256 && i < xW; i += 2)
            if (x[i] != 0) { x64 = 0; break; }
        long long E;
        if (elemMode) E = eiW / 2;
        else          E = e64 ? eiW / 4 : eiW / 2;
        if (E > EE) E = EE;
        if (E < 0)  E = 0;
        g_E = (int)E;
        g_e64 = e64;
        g_x64 = x64;
    }
}

// ---------------- CSR build ----------------
__global__ void zero_deg_kernel(int n) {
    int i = blockIdx.x * blockDim.x + threadIdx.x;
    if (i < n) g_deg[i] = 0;
}

__global__ void count_kernel(const int* __restrict__ ei, int n) {
    int i = blockIdx.x * blockDim.x + threadIdx.x;
    int E = g_E;
    if (i >= E) return;
    int e64 = g_e64;
    long long dstBase = e64 ? 2LL * E : (long long)E;
    int d = e64 ? ei[dstBase + 2LL * i] : ei[dstBase + i];
    d = max(0, min(d, n - 1));
    atomicAdd(&g_deg[d], 1);
}

__global__ void scan_kernel(int n) {
    __shared__ int s[1024];
    const int C = (n + 1023) / 1024;
    int t = threadIdx.x;
    int start = t * C;
    int end = start + C; if (end > n) end = n;
    if (start > n) start = n;
    int sum = 0;
    for (int i = start; i < end; i++) sum += g_deg[i];
    s[t] = sum;
    __syncthreads();
    for (int d = 1; d < 1024; d <<= 1) {
        int v = (t >= d) ? s[t - d] : 0;
        __syncthreads();
        s[t] += v;
        __syncthreads();
    }
    int run = s[t] - sum;
    for (int i = start; i < end; i++) {
        g_off[i] = run;
        g_cur[i] = run;
        run += g_deg[i];
    }
    if (t == 1023) g_off[n] = s[1023];
}

__global__ void fill_kernel(const int* __restrict__ ei, int n) {
    int i = blockIdx.x * blockDim.x + threadIdx.x;
    int E = g_E;
    if (i >= E) return;
    int e64 = g_e64;
    long long dstBase = e64 ? 2LL * E : (long long)E;
    int sv = e64 ? ei[2LL * i] : ei[i];
    int dv = e64 ? ei[dstBase + 2LL * i] : ei[dstBase + i];
    sv = max(0, min(sv, n - 1));
    dv = max(0, min(dv, n - 1));
    int pos = atomicAdd(&g_cur[dv], 1);
    if (pos < EE) g_csr[pos] = sv;
}

// ---------------- embedding gather (writes g_h via direct global ref) --------
__global__ void gather_kernel(const int* __restrict__ x, const float* __restrict__ emb,
                              int n, long long embRows) {
    int idx = blockIdx.x * blockDim.x + threadIdx.x;
    if (idx >= n * 32) return;
    int node = idx >> 5;
    int c4 = (idx & 31) * 4;
    long long row = g_x64 ? (long long)x[2LL * node] : (long long)x[node];
    if (row < 0) row = 0;
    if (row >= embRows) row = embRows - 1;
    float4 v = *(const float4*)(emb + row * 128 + c4);
    *(float4*)(g_h + (long long)node * 128 + c4) = v;
}

// ---------------- weight prep ----------------
__global__ void prep_wt_kernel(const float* __restrict__ W1l, const float* __restrict__ W1r,
                               const float* __restrict__ W2l, const float* __restrict__ W2r) {
    int idx = blockIdx.x * blockDim.x + threadIdx.x;
    if (idx >= 2 * 256 * 128) return;
    int which = idx >> 15;
    int rem = idx & 32767;
    int k = rem >> 7;
    int o = rem & 127;
    const float* Wl = which ? W2l : W1l;
    const float* Wr = which ? W2r : W1r;
    float v = (k < 128) ? Wl[o * 128 + k] : Wr[o * 128 + (k - 128)];
    (which ? g_WT2 : g_WT1)[k * 128 + o] = v;
}

// ---------------- mean aggregation: one warp per node ----------------
__global__ void aggregate_kernel(const float* __restrict__ hin, int n) {
    int gwarp = (blockIdx.x * blockDim.x + threadIdx.x) >> 5;
    int lane = threadIdx.x & 31;
    if (gwarp >= n) return;
    int beg = g_off[gwarp];
    int end = g_off[gwarp + 1];
    float ax = 0.f, ay = 0.f, az = 0.f, aw = 0.f;
    for (int e = beg; e < end; e++) {
        int s = __ldg(&g_csr[e]);
        s = max(0, min(s, n - 1));
        float4 v = *(const float4*)(hin + (long long)s * 128 + lane * 4);
        ax += v.x; ay += v.y; az += v.z; aw += v.w;
    }
    float inv = 1.0f / fmaxf((float)(end - beg), 1.0f);
    float4 r; r.x = ax * inv; r.y = ay * inv; r.z = az * inv; r.w = aw * inv;
    *(float4*)(g_agg + (long long)gwarp * 128 + lane * 4) = r;
}

// ---------------- fused dual GEMM + bias + relu ----------------
#define BM 128
#define BN 128
#define BK 16
#define TM 8
#define TN 8

__global__ __launch_bounds__(256, 2)
void gemm_kernel(const float* __restrict__ A0,   // agg [N,128]
                 const float* __restrict__ A1,   // h   [N,128]
                 const float* __restrict__ WT,   // [256,128]
                 const float* __restrict__ bias, // [128]
                 float* __restrict__ out, int n) {
    __shared__ float As[BM][BK + 1];
    __shared__ float Bs[BK][BN];

    int tid = threadIdx.x;
    int tx = tid & 15;
    int ty = tid >> 4;
    int rowBase = blockIdx.x * BM;

    float acc[TM][TN];
#pragma unroll
    for (int r = 0; r < TM; r++)
#pragma unroll
        for (int j = 0; j < TN; j++) acc[r][j] = 0.f;

    for (int kc = 0; kc < 16; kc++) {
        const float* A = (kc < 8) ? A0 : A1;
        int kcol = (kc & 7) * BK;

#pragma unroll
        for (int i = 0; i < 2; i++) {
            int f = tid + i * 256;
            int r = f >> 2;
            int c4 = (f & 3) * 4;
            int gr = rowBase + r;
            float4 v = make_float4(0.f, 0.f, 0.f, 0.f);
            if (gr < n) v = *(const float4*)(A + (long long)gr * 128 + kcol + c4);
            As[r][c4 + 0] = v.x; As[r][c4 + 1] = v.y;
            As[r][c4 + 2] = v.z; As[r][c4 + 3] = v.w;
        }
#pragma unroll
        for (int i = 0; i < 2; i++) {
            int f = tid + i * 256;
            int kk = f >> 5;
            int o4 = (f & 31) * 4;
            *(float4*)&Bs[kk][o4] = *(const float4*)(WT + (kc * BK + kk) * 128 + o4);
        }
        __syncthreads();

#pragma unroll
        for (int kk = 0; kk < BK; kk++) {
            float a[TM], b[TN];
#pragma unroll
            for (int r = 0; r < TM; r++) a[r] = As[ty * TM + r][kk];
#pragma unroll
            for (int j = 0; j < TN; j++) b[j] = Bs[kk][tx * TN + j];
#pragma unroll
            for (int r = 0; r < TM; r++)
#pragma unroll
                for (int j = 0; j < TN; j++) acc[r][j] += a[r] * b[j];
        }
        __syncthreads();
    }

    float bv[TN];
#pragma unroll
    for (int j = 0; j < TN; j++) bv[j] = __ldg(&bias[tx * TN + j]);

#pragma unroll
    for (int r = 0; r < TM; r++) {
        int gr = rowBase + ty * TM + r;
        if (gr < n) {
            float4 v0, v1;
            v0.x = fmaxf(acc[r][0] + bv[0], 0.f);
            v0.y = fmaxf(acc[r][1] + bv[1], 0.f);
            v0.z = fmaxf(acc[r][2] + bv[2], 0.f);
            v0.w = fmaxf(acc[r][3] + bv[3], 0.f);
            v1.x = fmaxf(acc[r][4] + bv[4], 0.f);
            v1.y = fmaxf(acc[r][5] + bv[5], 0.f);
            v1.z = fmaxf(acc[r][6] + bv[6], 0.f);
            v1.w = fmaxf(acc[r][7] + bv[7], 0.f);
            float* op = out + (long long)gr * 128 + tx * TN;
            *(float4*)op = v0;
            *(float4*)(op + 4) = v1;
        }
    }
}

// ---------------- launch ----------------
extern "C" void kernel_launch(void* const* d_in, const int* in_sizes, int n_in,
                              void* d_out, int out_size) {
    // ---- rank-based classification: emb > edge > x > 4x weights > 2x biases ----
    long long sz[32];
    int used[32];
    int m = n_in > 32 ? 32 : n_in;
    for (int i = 0; i < m; i++) { sz[i] = (long long)in_sizes[i]; used[i] = 0; }

    int iEmb = -1, iEdge = -1, iX = -1;
    for (int pass = 0; pass < 3; pass++) {
        long long best = -1; int bi = -1;
        for (int i = 0; i < m; i++)
            if (!used[i] && sz[i] > best) { best = sz[i]; bi = i; }
        used[bi] = 1;
        if (pass == 0) iEmb = bi; else if (pass == 1) iEdge = bi; else iX = bi;
    }
    long long wsz = -1;
    for (int i = 0; i < m; i++) if (!used[i] && sz[i] > wsz) wsz = sz[i];
    const float* Wlist[4] = {0, 0, 0, 0};
    const float* blist[2] = {0, 0};
    int nW = 0, nb = 0;
    for (int i = 0; i < m; i++) {
        if (used[i]) continue;
        if (sz[i] == wsz && nW < 4) Wlist[nW++] = (const float*)d_in[i];
        else if (nb < 2)            blist[nb++] = (const float*)d_in[i];
    }

    const float* emb = (const float*)d_in[iEmb];
    const int*   ei  = (const int*)d_in[iEdge];
    const int*   x   = (const int*)d_in[iX];

    int bytesMode = (sz[iEmb] > 300000000LL) ? 1 : 0;
    long long div = bytesMode ? 4 : 1;
    long long embRows = sz[iEmb] / div / 128;
    long long N_ll = (long long)out_size / (128 * div);
    if (N_ll < 1) N_ll = 1;
    if (N_ll > NN) N_ll = NN;
    int N = (int)N_ll;

    long long eiW = sz[iEdge] / div;
    long long xW  = sz[iX]   / div;
    int elemMode = bytesMode ? 0 : 1;

    long long Emax = eiW / 2; if (Emax > EE) Emax = EE; if (Emax < 1) Emax = 1;

    const float* W1l = Wlist[0];
    const float* W1r = Wlist[1];
    const float* W2l = Wlist[2];
    const float* W2r = Wlist[3];
    const float* b1  = blist[0];
    const float* b2  = blist[1];
    float* out = (float*)d_out;

    // ---- THE FIX: resolve true device addresses of __device__ globals.
    // Passing the symbol directly from host code passes the host shadow
    // address, which GB300's ATS happily dereferences as host memory (zeros).
    float *p_h = nullptr, *p_h2 = nullptr, *p_agg = nullptr, *p_WT1 = nullptr, *p_WT2 = nullptr;
    cudaGetSymbolAddress((void**)&p_h,   g_h);
    cudaGetSymbolAddress((void**)&p_h2,  g_h2);
    cudaGetSymbolAddress((void**)&p_agg, g_agg);
    cudaGetSymbolAddress((void**)&p_WT1, g_WT1);
    cudaGetSymbolAddress((void**)&p_WT2, g_WT2);

    // ---- pipeline ----
    detect_kernel<<<1, 32>>>(ei, eiW, x, xW, elemMode);
    zero_deg_kernel<<<(N + 255) / 256, 256>>>(N);
    count_kernel<<<(int)((Emax + 255) / 256), 256>>>(ei, N);
    scan_kernel<<<1, 1024>>>(N);
    fill_kernel<<<(int)((Emax + 255) / 256), 256>>>(ei, N);

    gather_kernel<<<(N * 32 + 255) / 256, 256>>>(x, emb, N, embRows);
    prep_wt_kernel<<<(65536 + 255) / 256, 256>>>(W1l, W1r, W2l, W2r);

    int aggBlocks = (N * 32 + 255) / 256;
    int gemmBlocks = (N + BM - 1) / BM;

    aggregate_kernel<<<aggBlocks, 256>>>(p_h, N);
    gemm_kernel<<<gemmBlocks, 256>>>(p_agg, p_h, p_WT1, b1, p_h2, N);

    aggregate_kernel<<<aggBlocks, 256>>>(p_h2, N);
    gemm_kernel<<<gemmBlocks, 256>>>(p_agg, p_h2, p_WT2, b2, out, N);
}

// round 6
// speedup vs baseline: 1.3377x; 1.3377x over previous
#include <cuda_runtime.h>
#include <cuda_bf16.h>

#define NN 50000        // capacity: nodes
#define EE 800000       // capacity: edges
#define HID 128

// ---------------- scratch (static __device__, no allocation) ----------------
__device__ float g_h[NN * 128];
__device__ float g_h2[NN * 128];
__device__ float g_agg[NN * 128];
__device__ int   g_deg[NN];
__device__ int   g_off[NN + 1];
__device__ int   g_cur[NN];
__device__ int   g_csr[EE];
__device__ float g_WT1[256 * 128];
__device__ float g_WT2[256 * 128];
__device__ int   g_bsum[256];
__device__ int   g_bscan[256];
__device__ int   g_E;        // true edge count (device-detected)
__device__ int   g_e64;      // edge_index is int64
__device__ int   g_x64;      // x is int64

// ---------------- f32x2 helpers ----------------
__device__ __forceinline__ unsigned long long fma2(unsigned long long a,
                                                   unsigned long long b,
                                                   unsigned long long c) {
    unsigned long long d;
    asm("fma.rn.f32x2 %0, %1, %2, %3;" : "=l"(d) : "l"(a), "l"(b), "l"(c));
    return d;
}
__device__ __forceinline__ unsigned long long pack2(float x) {
    unsigned long long d;
    unsigned int u = __float_as_uint(x);
    asm("mov.b64 %0, {%1, %1};" : "=l"(d) : "r"(u));
    return d;
}
__device__ __forceinline__ float2 unpack2(unsigned long long v) {
    unsigned int lo, hi;
    asm("mov.b64 {%0, %1}, %2;" : "=r"(lo), "=r"(hi) : "l"(v));
    return make_float2(__uint_as_float(lo), __uint_as_float(hi));
}

// ---------------- dtype / count detection ----------------
__global__ void detect_kernel(const int* __restrict__ ei, long long eiW,
                              const int* __restrict__ x, long long xW,
                              int elemMode) {
    if (blockIdx.x == 0 && threadIdx.x == 0) {
        int e64 = 1;
        for (long long i = 1; i < 256 && i < eiW; i += 2)
            if (ei[i] != 0) { e64 = 0; break; }
        int x64 = 1;
        for (long long i = 1; i < 256 && i < xW; i += 2)
            if (x[i] != 0) { x64 = 0; break; }
        long long E;
        if (elemMode) E = eiW / 2;
        else          E = e64 ? eiW / 4 : eiW / 2;
        if (E > EE) E = EE;
        if (E < 0)  E = 0;
        g_E = (int)E;
        g_e64 = e64;
        g_x64 = x64;
    }
}

// ---------------- CSR build ----------------
__global__ void zero_deg_kernel(int n) {
    int i = blockIdx.x * blockDim.x + threadIdx.x;
    if (i < n) g_deg[i] = 0;
}

__global__ void count_kernel(const int* __restrict__ ei, int n) {
    int i = blockIdx.x * blockDim.x + threadIdx.x;
    int E = g_E;
    if (i >= E) return;
    int e64 = g_e64;
    long long dstBase = e64 ? 2LL * E : (long long)E;
    int d = e64 ? ei[dstBase + 2LL * i] : ei[dstBase + i];
    d = max(0, min(d, n - 1));
    atomicAdd(&g_deg[d], 1);
}

// ---- two-level scan (replaces 78us single-block scan) ----
__global__ void blocksum_kernel(int n) {
    __shared__ int s[256];
    int t = threadIdx.x;
    int i = blockIdx.x * 256 + t;
    int v = (i < n) ? g_deg[i] : 0;
    s[t] = v;
    __syncthreads();
    for (int d = 128; d > 0; d >>= 1) {
        if (t < d) s[t] += s[t + d];
        __syncthreads();
    }
    if (t == 0) g_bsum[blockIdx.x] = s[0];
}

__global__ void scan_bsum_kernel(int nb) {
    __shared__ int s[256];
    int t = threadIdx.x;
    int v = (t < nb) ? g_bsum[t] : 0;
    s[t] = v;
    __syncthreads();
    for (int d = 1; d < 256; d <<= 1) {
        int u = (t >= d) ? s[t - d] : 0;
        __syncthreads();
        s[t] += u;
        __syncthreads();
    }
    g_bscan[t] = s[t] - v;   // exclusive
}

__global__ void write_off_kernel(int n) {
    __shared__ int s[256];
    int t = threadIdx.x;
    int i = blockIdx.x * 256 + t;
    int v = (i < n) ? g_deg[i] : 0;
    s[t] = v;
    __syncthreads();
    for (int d = 1; d < 256; d <<= 1) {
        int u = (t >= d) ? s[t - d] : 0;
        __syncthreads();
        s[t] += u;
        __syncthreads();
    }
    int excl = s[t] - v + g_bscan[blockIdx.x];
    if (i < n) {
        g_off[i] = excl;
        g_cur[i] = excl;
        if (i == n - 1) g_off[n] = excl + v;
    }
}

__global__ void fill_kernel(const int* __restrict__ ei, int n) {
    int i = blockIdx.x * blockDim.x + threadIdx.x;
    int E = g_E;
    if (i >= E) return;
    int e64 = g_e64;
    long long dstBase = e64 ? 2LL * E : (long long)E;
    int sv = e64 ? ei[2LL * i] : ei[i];
    int dv = e64 ? ei[dstBase + 2LL * i] : ei[dstBase + i];
    sv = max(0, min(sv, n - 1));
    dv = max(0, min(dv, n - 1));
    int pos = atomicAdd(&g_cur[dv], 1);
    if (pos < EE) g_csr[pos] = sv;
}

// ---------------- embedding gather ----------------
__global__ void gather_kernel(const int* __restrict__ x, const float* __restrict__ emb,
                              int n, long long embRows) {
    int idx = blockIdx.x * blockDim.x + threadIdx.x;
    if (idx >= n * 32) return;
    int node = idx >> 5;
    int c4 = (idx & 31) * 4;
    long long row = g_x64 ? (long long)x[2LL * node] : (long long)x[node];
    if (row < 0) row = 0;
    if (row >= embRows) row = embRows - 1;
    float4 v = *(const float4*)(emb + row * 128 + c4);
    *(float4*)(g_h + (long long)node * 128 + c4) = v;
}

// ---------------- weight prep ----------------
__global__ void prep_wt_kernel(const float* __restrict__ W1l, const float* __restrict__ W1r,
                               const float* __restrict__ W2l, const float* __restrict__ W2r) {
    int idx = blockIdx.x * blockDim.x + threadIdx.x;
    if (idx >= 2 * 256 * 128) return;
    int which = idx >> 15;
    int rem = idx & 32767;
    int k = rem >> 7;
    int o = rem & 127;
    const float* Wl = which ? W2l : W1l;
    const float* Wr = which ? W2r : W1r;
    float v = (k < 128) ? Wl[o * 128 + k] : Wr[o * 128 + (k - 128)];
    (which ? g_WT2 : g_WT1)[k * 128 + o] = v;
}

// ---------------- mean aggregation: one warp per node ----------------
__global__ void aggregate_kernel(const float* __restrict__ hin, int n) {
    int gwarp = (blockIdx.x * blockDim.x + threadIdx.x) >> 5;
    int lane = threadIdx.x & 31;
    if (gwarp >= n) return;
    int beg = g_off[gwarp];
    int end = g_off[gwarp + 1];
    float ax = 0.f, ay = 0.f, az = 0.f, aw = 0.f;
    for (int e = beg; e < end; e++) {
        int s = __ldg(&g_csr[e]);
        s = max(0, min(s, n - 1));
        float4 v = *(const float4*)(hin + (long long)s * 128 + lane * 4);
        ax += v.x; ay += v.y; az += v.z; aw += v.w;
    }
    float inv = 1.0f / fmaxf((float)(end - beg), 1.0f);
    float4 r; r.x = ax * inv; r.y = ay * inv; r.z = az * inv; r.w = aw * inv;
    *(float4*)(g_agg + (long long)gwarp * 128 + lane * 4) = r;
}

// ---------------- fused dual GEMM + bias + relu (FFMA2 / f32x2) ----------------
// out[i,o] = relu( sum_k agg[i,k]*WT[k,o] + sum_k h[i,k]*WT[128+k,o] + bias[o] )
// Thread (tx,ty): rows ty*8..ty*8+7, column pairs {32*jj + 2*tx | jj=0..3}.
#define BM 128
#define BN 128
#define BK 16
#define TM 8

__global__ __launch_bounds__(256, 2)
void gemm_kernel(const float* __restrict__ A0,   // agg [N,128]
                 const float* __restrict__ A1,   // h   [N,128]
                 const float* __restrict__ WT,   // [256,128]
                 const float* __restrict__ bias, // [128]
                 float* __restrict__ out, int n) {
    __shared__ unsigned long long As2[BM][BK + 1];  // pre-duplicated (a,a) pairs
    __shared__ float Bs[BK][BN];

    int tid = threadIdx.x;
    int tx = tid & 15;
    int ty = tid >> 4;
    int rowBase = blockIdx.x * BM;

    unsigned long long acc[TM][4];
#pragma unroll
    for (int r = 0; r < TM; r++)
#pragma unroll
        for (int j = 0; j < 4; j++) acc[r][j] = 0ULL;

    for (int kc = 0; kc < 16; kc++) {
        const float* A = (kc < 8) ? A0 : A1;
        int kcol = (kc & 7) * BK;

        // A tile: 128x16 floats, duplicated into u64 pairs
#pragma unroll
        for (int i = 0; i < 2; i++) {
            int f = tid + i * 256;
            int r = f >> 2;
            int c4 = (f & 3) * 4;
            int gr = rowBase + r;
            float4 v = make_float4(0.f, 0.f, 0.f, 0.f);
            if (gr < n) v = *(const float4*)(A + (long long)gr * 128 + kcol + c4);
            As2[r][c4 + 0] = pack2(v.x);
            As2[r][c4 + 1] = pack2(v.y);
            As2[r][c4 + 2] = pack2(v.z);
            As2[r][c4 + 3] = pack2(v.w);
        }
        // B tile: 16x128, coalesced
#pragma unroll
        for (int i = 0; i < 2; i++) {
            int f = tid + i * 256;
            int kk = f >> 5;
            int o4 = (f & 31) * 4;
            *(float4*)&Bs[kk][o4] = *(const float4*)(WT + (kc * BK + kk) * 128 + o4);
        }
        __syncthreads();

#pragma unroll
        for (int kk = 0; kk < BK; kk++) {
            unsigned long long a2[TM];
#pragma unroll
            for (int r = 0; r < TM; r++) a2[r] = As2[ty * TM + r][kk];
            unsigned long long b2[4];
            const unsigned long long* bp = (const unsigned long long*)&Bs[kk][0];
#pragma unroll
            for (int j = 0; j < 4; j++) b2[j] = bp[j * 16 + tx];
#pragma unroll
            for (int r = 0; r < TM; r++)
#pragma unroll
                for (int j = 0; j < 4; j++) acc[r][j] = fma2(a2[r], b2[j], acc[r][j]);
        }
        __syncthreads();
    }

    float2 bv[4];
#pragma unroll
    for (int j = 0; j < 4; j++) bv[j] = *(const float2*)&bias[j * 32 + tx * 2];

#pragma unroll
    for (int r = 0; r < TM; r++) {
        int gr = rowBase + ty * TM + r;
        if (gr < n) {
            float* op = out + (long long)gr * 128;
#pragma unroll
            for (int j = 0; j < 4; j++) {
                float2 p = unpack2(acc[r][j]);
                p.x = fmaxf(p.x + bv[j].x, 0.f);
                p.y = fmaxf(p.y + bv[j].y, 0.f);
                *(float2*)(op + j * 32 + tx * 2) = p;
            }
        }
    }
}

// ---------------- launch ----------------
extern "C" void kernel_launch(void* const* d_in, const int* in_sizes, int n_in,
                              void* d_out, int out_size) {
    // ---- rank-based classification: emb > edge > x > 4x weights > 2x biases ----
    long long sz[32];
    int used[32];
    int m = n_in > 32 ? 32 : n_in;
    for (int i = 0; i < m; i++) { sz[i] = (long long)in_sizes[i]; used[i] = 0; }

    int iEmb = -1, iEdge = -1, iX = -1;
    for (int pass = 0; pass < 3; pass++) {
        long long best = -1; int bi = -1;
        for (int i = 0; i < m; i++)
            if (!used[i] && sz[i] > best) { best = sz[i]; bi = i; }
        used[bi] = 1;
        if (pass == 0) iEmb = bi; else if (pass == 1) iEdge = bi; else iX = bi;
    }
    long long wsz = -1;
    for (int i = 0; i < m; i++) if (!used[i] && sz[i] > wsz) wsz = sz[i];
    const float* Wlist[4] = {0, 0, 0, 0};
    const float* blist[2] = {0, 0};
    int nW = 0, nb = 0;
    for (int i = 0; i < m; i++) {
        if (used[i]) continue;
        if (sz[i] == wsz && nW < 4) Wlist[nW++] = (const float*)d_in[i];
        else if (nb < 2)            blist[nb++] = (const float*)d_in[i];
    }

    const float* emb = (const float*)d_in[iEmb];
    const int*   ei  = (const int*)d_in[iEdge];
    const int*   x   = (const int*)d_in[iX];

    int bytesMode = (sz[iEmb] > 300000000LL) ? 1 : 0;
    long long div = bytesMode ? 4 : 1;
    long long embRows = sz[iEmb] / div / 128;
    long long N_ll = (long long)out_size / (128 * div);
    if (N_ll < 1) N_ll = 1;
    if (N_ll > NN) N_ll = NN;
    int N = (int)N_ll;

    long long eiW = sz[iEdge] / div;
    long long xW  = sz[iX]   / div;
    int elemMode = bytesMode ? 0 : 1;

    long long Emax = eiW / 2; if (Emax > EE) Emax = EE; if (Emax < 1) Emax = 1;

    const float* W1l = Wlist[0];
    const float* W1r = Wlist[1];
    const float* W2l = Wlist[2];
    const float* W2r = Wlist[3];
    const float* b1  = blist[0];
    const float* b2  = blist[1];
    float* out = (float*)d_out;

    // resolve true device addresses of __device__ globals (ATS would silently
    // dereference the host shadow otherwise)
    float *p_h = nullptr, *p_h2 = nullptr, *p_agg = nullptr, *p_WT1 = nullptr, *p_WT2 = nullptr;
    cudaGetSymbolAddress((void**)&p_h,   g_h);
    cudaGetSymbolAddress((void**)&p_h2,  g_h2);
    cudaGetSymbolAddress((void**)&p_agg, g_agg);
    cudaGetSymbolAddress((void**)&p_WT1, g_WT1);
    cudaGetSymbolAddress((void**)&p_WT2, g_WT2);

    int nBlk = (N + 255) / 256;   // <= 196 for N<=50000

    // ---- pipeline ----
    detect_kernel<<<1, 32>>>(ei, eiW, x, xW, elemMode);
    zero_deg_kernel<<<nBlk, 256>>>(N);
    count_kernel<<<(int)((Emax + 255) / 256), 256>>>(ei, N);
    blocksum_kernel<<<nBlk, 256>>>(N);
    scan_bsum_kernel<<<1, 256>>>(nBlk);
    write_off_kernel<<<nBlk, 256>>>(N);
    fill_kernel<<<(int)((Emax + 255) / 256), 256>>>(ei, N);

    gather_kernel<<<(N * 32 + 255) / 256, 256>>>(x, emb, N, embRows);
    prep_wt_kernel<<<(65536 + 255) / 256, 256>>>(W1l, W1r, W2l, W2r);

    int aggBlocks = (N * 32 + 255) / 256;
    int gemmBlocks = (N + BM - 1) / BM;

    aggregate_kernel<<<aggBlocks, 256>>>(p_h, N);
    gemm_kernel<<<gemmBlocks, 256>>>(p_agg, p_h, p_WT1, b1, p_h2, N);

    aggregate_kernel<<<aggBlocks, 256>>>(p_h2, N);
    gemm_kernel<<<gemmBlocks, 256>>>(p_agg, p_h2, p_WT2, b2, out, N);
}

// round 8
// speedup vs baseline: 2.1088x; 1.5764x over previous
#include <cuda_runtime.h>
#include <cuda_bf16.h>
#include <cstdint>

#define NN 50000        // capacity: nodes
#define EE 800000       // capacity: edges
#define HID 128

// ---------------- scratch (static __device__, no allocation) ----------------
__device__ float g_h[NN * 128];
__device__ float g_h2[NN * 128];
__device__ float g_agg[NN * 128];
__device__ int   g_deg[NN];
__device__ int   g_off[NN + 1];
__device__ int   g_cur[NN];
__device__ int   g_csr[EE];
__device__ __nv_bfloat16 g_Bhi1[128 * 256];   // B[o][k] = {W1_l | W1_r} hi
__device__ __nv_bfloat16 g_Blo1[128 * 256];   // residual lo
__device__ __nv_bfloat16 g_Bhi2[128 * 256];
__device__ __nv_bfloat16 g_Blo2[128 * 256];
__device__ int   g_bsum[256];
__device__ int   g_bscan[256];
__device__ int   g_E;
__device__ int   g_e64;
__device__ int   g_x64;

// ---------------- warp-level bf16 MMA (plain PTX, no arch-'a' gating) -------
__device__ __forceinline__ void mma16816(float* d, const uint32_t* a, const uint32_t* b) {
    asm volatile(
        "mma.sync.aligned.m16n8k16.row.col.f32.bf16.bf16.f32 "
        "{%0,%1,%2,%3}, {%4,%5,%6,%7}, {%8,%9}, {%0,%1,%2,%3};"
        : "+f"(d[0]), "+f"(d[1]), "+f"(d[2]), "+f"(d[3])
        : "r"(a[0]), "r"(a[1]), "r"(a[2]), "r"(a[3]), "r"(b[0]), "r"(b[1]));
}

// ---------------- dtype / count detection ----------------
__global__ void detect_kernel(const int* __restrict__ ei, long long eiW,
                              const int* __restrict__ x, long long xW,
                              int elemMode) {
    if (blockIdx.x == 0 && threadIdx.x == 0) {
        int e64 = 1;
        for (long long i = 1; i < 256 && i < eiW; i += 2)
            if (ei[i] != 0) { e64 = 0; break; }
        int x64 = 1;
        for (long long i = 1; i < 256 && i < xW; i += 2)
            if (x[i] != 0) { x64 = 0; break; }
        long long E;
        if (elemMode) E = eiW / 2;
        else          E = e64 ? eiW / 4 : eiW / 2;
        if (E > EE) E = EE;
        if (E < 0)  E = 0;
        g_E = (int)E;
        g_e64 = e64;
        g_x64 = x64;
    }
}

// ---------------- CSR build ----------------
__global__ void zero_deg_kernel(int n) {
    int i = blockIdx.x * blockDim.x + threadIdx.x;
    if (i < n) g_deg[i] = 0;
}

__global__ void count_kernel(const int* __restrict__ ei, int n) {
    int i = blockIdx.x * blockDim.x + threadIdx.x;
    int E = g_E;
    if (i >= E) return;
    int e64 = g_e64;
    long long dstBase = e64 ? 2LL * E : (long long)E;
    int d = e64 ? ei[dstBase + 2LL * i] : ei[dstBase + i];
    d = max(0, min(d, n - 1));
    atomicAdd(&g_deg[d], 1);
}

__global__ void blocksum_kernel(int n) {
    __shared__ int s[256];
    int t = threadIdx.x;
    int i = blockIdx.x * 256 + t;
    int v = (i < n) ? g_deg[i] : 0;
    s[t] = v;
    __syncthreads();
    for (int d = 128; d > 0; d >>= 1) {
        if (t < d) s[t] += s[t + d];
        __syncthreads();
    }
    if (t == 0) g_bsum[blockIdx.x] = s[0];
}

__global__ void scan_bsum_kernel(int nb) {
    __shared__ int s[256];
    int t = threadIdx.x;
    int v = (t < nb) ? g_bsum[t] : 0;
    s[t] = v;
    __syncthreads();
    for (int d = 1; d < 256; d <<= 1) {
        int u = (t >= d) ? s[t - d] : 0;
        __syncthreads();
        s[t] += u;
        __syncthreads();
    }
    g_bscan[t] = s[t] - v;
}

__global__ void write_off_kernel(int n) {
    __shared__ int s[256];
    int t = threadIdx.x;
    int i = blockIdx.x * 256 + t;
    int v = (i < n) ? g_deg[i] : 0;
    s[t] = v;
    __syncthreads();
    for (int d = 1; d < 256; d <<= 1) {
        int u = (t >= d) ? s[t - d] : 0;
        __syncthreads();
        s[t] += u;
        __syncthreads();
    }
    int excl = s[t] - v + g_bscan[blockIdx.x];
    if (i < n) {
        g_off[i] = excl;
        g_cur[i] = excl;
        if (i == n - 1) g_off[n] = excl + v;
    }
}

__global__ void fill_kernel(const int* __restrict__ ei, int n) {
    int i = blockIdx.x * blockDim.x + threadIdx.x;
    int E = g_E;
    if (i >= E) return;
    int e64 = g_e64;
    long long dstBase = e64 ? 2LL * E : (long long)E;
    int sv = e64 ? ei[2LL * i] : ei[i];
    int dv = e64 ? ei[dstBase + 2LL * i] : ei[dstBase + i];
    sv = max(0, min(sv, n - 1));
    dv = max(0, min(dv, n - 1));
    int pos = atomicAdd(&g_cur[dv], 1);
    if (pos < EE) g_csr[pos] = sv;
}

// ---------------- embedding gather ----------------
__global__ void gather_kernel(const int* __restrict__ x, const float* __restrict__ emb,
                              int n, long long embRows) {
    int idx = blockIdx.x * blockDim.x + threadIdx.x;
    if (idx >= n * 32) return;
    int node = idx >> 5;
    int c4 = (idx & 31) * 4;
    long long row = g_x64 ? (long long)x[2LL * node] : (long long)x[node];
    if (row < 0) row = 0;
    if (row >= embRows) row = embRows - 1;
    float4 v = *(const float4*)(emb + row * 128 + c4);
    *(float4*)(g_h + (long long)node * 128 + c4) = v;
}

// ---------------- weight prep: split B = {Wl | Wr} into bf16 hi/lo ----------------
__global__ void prep_b_kernel(const float* __restrict__ W1l, const float* __restrict__ W1r,
                              const float* __restrict__ W2l, const float* __restrict__ W2r) {
    int idx = blockIdx.x * blockDim.x + threadIdx.x;   // 2*128*256 = 65536
    if (idx >= 2 * 128 * 256) return;
    int which = idx >> 15;
    int rem = idx & 32767;
    int o = rem >> 8;     // 0..127 output
    int k = rem & 255;    // 0..255
    const float* Wl = which ? W2l : W1l;
    const float* Wr = which ? W2r : W1r;
    float v = (k < 128) ? Wl[o * 128 + k] : Wr[o * 128 + (k - 128)];
    __nv_bfloat16 hi = __float2bfloat16(v);
    __nv_bfloat16 lo = __float2bfloat16(v - __bfloat162float(hi));
    (which ? g_Bhi2 : g_Bhi1)[o * 256 + k] = hi;
    (which ? g_Blo2 : g_Blo1)[o * 256 + k] = lo;
}

// ---------------- mean aggregation: one warp per node ----------------
__global__ void aggregate_kernel(const float* __restrict__ hin, int n) {
    int gwarp = (blockIdx.x * blockDim.x + threadIdx.x) >> 5;
    int lane = threadIdx.x & 31;
    if (gwarp >= n) return;
    int beg = g_off[gwarp];
    int end = g_off[gwarp + 1];
    float ax = 0.f, ay = 0.f, az = 0.f, aw = 0.f;
    for (int e = beg; e < end; e++) {
        int s = __ldg(&g_csr[e]);
        s = max(0, min(s, n - 1));
        float4 v = *(const float4*)(hin + (long long)s * 128 + lane * 4);
        ax += v.x; ay += v.y; az += v.z; aw += v.w;
    }
    float inv = 1.0f / fmaxf((float)(end - beg), 1.0f);
    float4 r; r.x = ax * inv; r.y = ay * inv; r.z = az * inv; r.w = aw * inv;
    *(float4*)(g_agg + (long long)gwarp * 128 + lane * 4) = r;
}

// ---------------- split-bf16 HMMA dual GEMM + bias + relu ----------------
// out[i,o] = relu( sum_k A[i,k]*B[o,k] + bias[o] ),  A = [agg | h] (K=256),
// B = [128,256] bf16 hi/lo in gmem.  D = Ah*Bh + Ah*Bl + Al*Bh, fp32 accum.
// Block: 128 rows x 128 cols; 8 warps, warp w -> rows w*16..w*16+15.
#define ASTRIDE 72   // bf16 elems per smem row (64 data + 8 pad) -> conflict-free

// dynamic smem offsets (bf16 elements)
#define SO_AH 0
#define SO_AL (128 * ASTRIDE)
#define SO_BH (2 * 128 * ASTRIDE)
#define SO_BL (3 * 128 * ASTRIDE)
#define SM_BYTES (4 * 128 * ASTRIDE * 2)

__global__ __launch_bounds__(256, 2)
void hmma_gemm_kernel(const float* __restrict__ A0,   // agg [N,128]
                      const float* __restrict__ A1,   // h   [N,128]
                      const __nv_bfloat16* __restrict__ Bhi,  // [128,256]
                      const __nv_bfloat16* __restrict__ Blo,
                      const float* __restrict__ bias,
                      float* __restrict__ out, int n) {
    extern __shared__ __nv_bfloat16 sm[];
    __nv_bfloat16* sAh = sm + SO_AH;
    __nv_bfloat16* sAl = sm + SO_AL;
    __nv_bfloat16* sBh = sm + SO_BH;
    __nv_bfloat16* sBl = sm + SO_BL;

    int tid = threadIdx.x;
    int wid = tid >> 5;
    int lid = tid & 31;
    int g = lid >> 2;       // group row (0..7)
    int tg = lid & 3;       // thread-in-group (k pairs)
    int rowBase = blockIdx.x * 128;
    int mrow = wid * 16;

    float acc[16][4];
#pragma unroll
    for (int t = 0; t < 16; t++)
#pragma unroll
        for (int j = 0; j < 4; j++) acc[t][j] = 0.f;

    for (int kc = 0; kc < 4; kc++) {
        const float* A = (kc < 2) ? A0 : A1;
        int kbase = (kc & 1) * 64;

        // ---- load A chunk: 128 rows x 64 fp32 -> split bf16 hi/lo ----
#pragma unroll
        for (int it = 0; it < 8; it++) {
            int idx = tid + it * 256;          // 0..2047 float4s
            int r = idx >> 4;
            int c4 = (idx & 15) * 4;
            int gr = rowBase + r;
            float4 v = make_float4(0.f, 0.f, 0.f, 0.f);
            if (gr < n) v = *(const float4*)(A + (long long)gr * 128 + kbase + c4);
            __nv_bfloat16 hx = __float2bfloat16(v.x), hy = __float2bfloat16(v.y);
            __nv_bfloat16 hz = __float2bfloat16(v.z), hw = __float2bfloat16(v.w);
            __nv_bfloat162 ph0; ph0.x = hx; ph0.y = hy;
            __nv_bfloat162 ph1; ph1.x = hz; ph1.y = hw;
            __nv_bfloat162 pl0, pl1;
            pl0.x = __float2bfloat16(v.x - __bfloat162float(hx));
            pl0.y = __float2bfloat16(v.y - __bfloat162float(hy));
            pl1.x = __float2bfloat16(v.z - __bfloat162float(hz));
            pl1.y = __float2bfloat16(v.w - __bfloat162float(hw));
            int so = r * ASTRIDE + c4;
            *(__nv_bfloat162*)(sAh + so)     = ph0;
            *(__nv_bfloat162*)(sAh + so + 2) = ph1;
            *(__nv_bfloat162*)(sAl + so)     = pl0;
            *(__nv_bfloat162*)(sAl + so + 2) = pl1;
        }
        // ---- load B chunk: 128 rows x 64 bf16 (hi and lo) ----
#pragma unroll
        for (int it = 0; it < 4; it++) {
            int idx = tid + it * 256;          // 0..1023 uint4s
            int r = idx >> 3;
            int q = idx & 7;
            uint4 vh = *(const uint4*)(Bhi + r * 256 + kc * 64 + q * 8);
            uint4 vl = *(const uint4*)(Blo + r * 256 + kc * 64 + q * 8);
            *(uint4*)(sBh + r * ASTRIDE + q * 8) = vh;
            *(uint4*)(sBl + r * ASTRIDE + q * 8) = vl;
        }
        __syncthreads();

        // ---- mma over 4 k16 steps ----
#pragma unroll
        for (int ks = 0; ks < 4; ks++) {
            int k0 = ks * 16;
            uint32_t ah[4], al[4];
            int ra = (mrow + g) * ASTRIDE + k0 + tg * 2;
            int rb = (mrow + g + 8) * ASTRIDE + k0 + tg * 2;
            ah[0] = *(const uint32_t*)(sAh + ra);
            ah[1] = *(const uint32_t*)(sAh + rb);
            ah[2] = *(const uint32_t*)(sAh + ra + 8);
            ah[3] = *(const uint32_t*)(sAh + rb + 8);
            al[0] = *(const uint32_t*)(sAl + ra);
            al[1] = *(const uint32_t*)(sAl + rb);
            al[2] = *(const uint32_t*)(sAl + ra + 8);
            al[3] = *(const uint32_t*)(sAl + rb + 8);
#pragma unroll
            for (int nt = 0; nt < 16; nt++) {
                int nb = (nt * 8 + g) * ASTRIDE + k0 + tg * 2;
                uint32_t bh[2], bl[2];
                bh[0] = *(const uint32_t*)(sBh + nb);
                bh[1] = *(const uint32_t*)(sBh + nb + 8);
                bl[0] = *(const uint32_t*)(sBl + nb);
                bl[1] = *(const uint32_t*)(sBl + nb + 8);
                mma16816(acc[nt], ah, bh);
                mma16816(acc[nt], ah, bl);
                mma16816(acc[nt], al, bh);
            }
        }
        __syncthreads();
    }

    // ---- epilogue: bias + relu, float2 stores ----
    int gr0 = rowBase + mrow + g;
    int gr1 = gr0 + 8;
#pragma unroll
    for (int nt = 0; nt < 16; nt++) {
        int col = nt * 8 + tg * 2;
        float2 bb = *(const float2*)(bias + col);
        if (gr0 < n) {
            float2 o0;
            o0.x = fmaxf(acc[nt][0] + bb.x, 0.f);
            o0.y = fmaxf(acc[nt][1] + bb.y, 0.f);
            *(float2*)(out + (long long)gr0 * 128 + col) = o0;
        }
        if (gr1 < n) {
            float2 o1;
            o1.x = fmaxf(acc[nt][2] + bb.x, 0.f);
            o1.y = fmaxf(acc[nt][3] + bb.y, 0.f);
            *(float2*)(out + (long long)gr1 * 128 + col) = o1;
        }
    }
}

// ---------------- launch ----------------
extern "C" void kernel_launch(void* const* d_in, const int* in_sizes, int n_in,
                              void* d_out, int out_size) {
    // ---- rank-based classification: emb > edge > x > 4x weights > 2x biases ----
    long long sz[32];
    int used[32];
    int m = n_in > 32 ? 32 : n_in;
    for (int i = 0; i < m; i++) { sz[i] = (long long)in_sizes[i]; used[i] = 0; }

    int iEmb = -1, iEdge = -1, iX = -1;
    for (int pass = 0; pass < 3; pass++) {
        long long best = -1; int bi = -1;
        for (int i = 0; i < m; i++)
            if (!used[i] && sz[i] > best) { best = sz[i]; bi = i; }
        used[bi] = 1;
        if (pass == 0) iEmb = bi; else if (pass == 1) iEdge = bi; else iX = bi;
    }
    long long wsz = -1;
    for (int i = 0; i < m; i++) if (!used[i] && sz[i] > wsz) wsz = sz[i];
    const float* Wlist[4] = {0, 0, 0, 0};
    const float* blist[2] = {0, 0};
    int nW = 0, nb = 0;
    for (int i = 0; i < m; i++) {
        if (used[i]) continue;
        if (sz[i] == wsz && nW < 4) Wlist[nW++] = (const float*)d_in[i];
        else if (nb < 2)            blist[nb++] = (const float*)d_in[i];
    }

    const float* emb = (const float*)d_in[iEmb];
    const int*   ei  = (const int*)d_in[iEdge];
    const int*   x   = (const int*)d_in[iX];

    int bytesMode = (sz[iEmb] > 300000000LL) ? 1 : 0;
    long long div = bytesMode ? 4 : 1;
    long long embRows = sz[iEmb] / div / 128;
    long long N_ll = (long long)out_size / (128 * div);
    if (N_ll < 1) N_ll = 1;
    if (N_ll > NN) N_ll = NN;
    int N = (int)N_ll;

    long long eiW = sz[iEdge] / div;
    long long xW  = sz[iX]   / div;
    int elemMode = bytesMode ? 0 : 1;

    long long Emax = eiW / 2; if (Emax > EE) Emax = EE; if (Emax < 1) Emax = 1;

    const float* W1l = Wlist[0];
    const float* W1r = Wlist[1];
    const float* W2l = Wlist[2];
    const float* W2r = Wlist[3];
    const float* b1  = blist[0];
    const float* b2  = blist[1];
    float* out = (float*)d_out;

    // resolve true device addresses of __device__ globals (ATS trap otherwise)
    float *p_h = nullptr, *p_h2 = nullptr, *p_agg = nullptr;
    __nv_bfloat16 *p_bhi1 = nullptr, *p_blo1 = nullptr, *p_bhi2 = nullptr, *p_blo2 = nullptr;
    cudaGetSymbolAddress((void**)&p_h,    g_h);
    cudaGetSymbolAddress((void**)&p_h2,   g_h2);
    cudaGetSymbolAddress((void**)&p_agg,  g_agg);
    cudaGetSymbolAddress((void**)&p_bhi1, g_Bhi1);
    cudaGetSymbolAddress((void**)&p_blo1, g_Blo1);
    cudaGetSymbolAddress((void**)&p_bhi2, g_Bhi2);
    cudaGetSymbolAddress((void**)&p_blo2, g_Blo2);

    cudaFuncSetAttribute(hmma_gemm_kernel,
                         cudaFuncAttributeMaxDynamicSharedMemorySize, SM_BYTES);

    int nBlk = (N + 255) / 256;

    // ---- pipeline ----
    detect_kernel<<<1, 32>>>(ei, eiW, x, xW, elemMode);
    zero_deg_kernel<<<nBlk, 256>>>(N);
    count_kernel<<<(int)((Emax + 255) / 256), 256>>>(ei, N);
    blocksum_kernel<<<nBlk, 256>>>(N);
    scan_bsum_kernel<<<1, 256>>>(nBlk);
    write_off_kernel<<<nBlk, 256>>>(N);
    fill_kernel<<<(int)((Emax + 255) / 256), 256>>>(ei, N);

    gather_kernel<<<(N * 32 + 255) / 256, 256>>>(x, emb, N, embRows);
    prep_b_kernel<<<(65536 + 255) / 256, 256>>>(W1l, W1r, W2l, W2r);

    int aggBlocks = (N * 32 + 255) / 256;
    int gemmBlocks = (N + 127) / 128;

    aggregate_kernel<<<aggBlocks, 256>>>(p_h, N);
    hmma_gemm_kernel<<<gemmBlocks, 256, SM_BYTES>>>(p_agg, p_h, p_bhi1, p_blo1, b1, p_h2, N);

    aggregate_kernel<<<aggBlocks, 256>>>(p_h2, N);
    hmma_gemm_kernel<<<gemmBlocks, 256, SM_BYTES>>>(p_agg, p_h2, p_bhi2, p_blo2, b2, out, N);
}

// round 9
// speedup vs baseline: 2.1422x; 1.0159x over previous
#include <cuda_runtime.h>
#include <cuda_bf16.h>
#include <cuda_fp16.h>
#include <cstdint>

#define NN 50000        // capacity: nodes
#define EE 800000       // capacity: edges
#define HID 128

// ---------------- scratch (static __device__, no allocation) ----------------
__device__ float g_h[NN * 128];
__device__ float g_h2[NN * 128];
__device__ float g_agg[NN * 128];
__device__ __half g_hx[NN * 128];    // fp16 copy of h   (aggregation input L1)
__device__ __half g_h2x[NN * 128];   // fp16 copy of h2  (aggregation input L2)
__device__ int   g_deg[NN];
__device__ int   g_off[NN + 1];
__device__ int   g_cur[NN];
__device__ int   g_csr[EE];
__device__ __nv_bfloat16 g_Bhi1[128 * 256];   // B[o][k] = {W1_l | W1_r} hi
__device__ __nv_bfloat16 g_Blo1[128 * 256];   // residual lo
__device__ __nv_bfloat16 g_Bhi2[128 * 256];
__device__ __nv_bfloat16 g_Blo2[128 * 256];
__device__ int   g_bsum[256];
__device__ int   g_bscan[256];
__device__ int   g_E;
__device__ int   g_e64;
__device__ int   g_x64;

// ---------------- warp-level bf16 MMA (plain PTX, no arch-'a' gating) -------
__device__ __forceinline__ void mma16816(float* d, const uint32_t* a, const uint32_t* b) {
    asm volatile(
        "mma.sync.aligned.m16n8k16.row.col.f32.bf16.bf16.f32 "
        "{%0,%1,%2,%3}, {%4,%5,%6,%7}, {%8,%9}, {%0,%1,%2,%3};"
        : "+f"(d[0]), "+f"(d[1]), "+f"(d[2]), "+f"(d[3])
        : "r"(a[0]), "r"(a[1]), "r"(a[2]), "r"(a[3]), "r"(b[0]), "r"(b[1]));
}

// ---------------- dtype / count detection ----------------
__global__ void detect_kernel(const int* __restrict__ ei, long long eiW,
                              const int* __restrict__ x, long long xW,
                              int elemMode) {
    if (blockIdx.x == 0 && threadIdx.x == 0) {
        int e64 = 1;
        for (long long i = 1; i < 256 && i < eiW; i += 2)
            if (ei[i] != 0) { e64 = 0; break; }
        int x64 = 1;
        for (long long i = 1; i < 256 && i < xW; i += 2)
            if (x[i] != 0) { x64 = 0; break; }
        long long E;
        if (elemMode) E = eiW / 2;
        else          E = e64 ? eiW / 4 : eiW / 2;
        if (E > EE) E = EE;
        if (E < 0)  E = 0;
        g_E = (int)E;
        g_e64 = e64;
        g_x64 = x64;
    }
}

// ---------------- CSR build ----------------
__global__ void zero_deg_kernel(int n) {
    int i = blockIdx.x * blockDim.x + threadIdx.x;
    if (i < n) g_deg[i] = 0;
}

__global__ void count_kernel(const int* __restrict__ ei, int n) {
    int i = blockIdx.x * blockDim.x + threadIdx.x;
    int E = g_E;
    if (i >= E) return;
    int e64 = g_e64;
    long long dstBase = e64 ? 2LL * E : (long long)E;
    int d = e64 ? ei[dstBase + 2LL * i] : ei[dstBase + i];
    d = max(0, min(d, n - 1));
    atomicAdd(&g_deg[d], 1);
}

__global__ void blocksum_kernel(int n) {
    __shared__ int s[256];
    int t = threadIdx.x;
    int i = blockIdx.x * 256 + t;
    int v = (i < n) ? g_deg[i] : 0;
    s[t] = v;
    __syncthreads();
    for (int d = 128; d > 0; d >>= 1) {
        if (t < d) s[t] += s[t + d];
        __syncthreads();
    }
    if (t == 0) g_bsum[blockIdx.x] = s[0];
}

__global__ void scan_bsum_kernel(int nb) {
    __shared__ int s[256];
    int t = threadIdx.x;
    int v = (t < nb) ? g_bsum[t] : 0;
    s[t] = v;
    __syncthreads();
    for (int d = 1; d < 256; d <<= 1) {
        int u = (t >= d) ? s[t - d] : 0;
        __syncthreads();
        s[t] += u;
        __syncthreads();
    }
    g_bscan[t] = s[t] - v;
}

__global__ void write_off_kernel(int n) {
    __shared__ int s[256];
    int t = threadIdx.x;
    int i = blockIdx.x * 256 + t;
    int v = (i < n) ? g_deg[i] : 0;
    s[t] = v;
    __syncthreads();
    for (int d = 1; d < 256; d <<= 1) {
        int u = (t >= d) ? s[t - d] : 0;
        __syncthreads();
        s[t] += u;
        __syncthreads();
    }
    int excl = s[t] - v + g_bscan[blockIdx.x];
    if (i < n) {
        g_off[i] = excl;
        g_cur[i] = excl;
        if (i == n - 1) g_off[n] = excl + v;
    }
}

__global__ void fill_kernel(const int* __restrict__ ei, int n) {
    int i = blockIdx.x * blockDim.x + threadIdx.x;
    int E = g_E;
    if (i >= E) return;
    int e64 = g_e64;
    long long dstBase = e64 ? 2LL * E : (long long)E;
    int sv = e64 ? ei[2LL * i] : ei[i];
    int dv = e64 ? ei[dstBase + 2LL * i] : ei[dstBase + i];
    sv = max(0, min(sv, n - 1));
    dv = max(0, min(dv, n - 1));
    int pos = atomicAdd(&g_cur[dv], 1);
    if (pos < EE) g_csr[pos] = sv;
}

// ---------------- embedding gather: fp32 + fp16 copies ----------------
__global__ void gather_kernel(const int* __restrict__ x, const float* __restrict__ emb,
                              int n, long long embRows) {
    int idx = blockIdx.x * blockDim.x + threadIdx.x;
    if (idx >= n * 32) return;
    int node = idx >> 5;
    int c4 = (idx & 31) * 4;
    long long row = g_x64 ? (long long)x[2LL * node] : (long long)x[node];
    if (row < 0) row = 0;
    if (row >= embRows) row = embRows - 1;
    float4 v = *(const float4*)(emb + row * 128 + c4);
    *(float4*)(g_h + (long long)node * 128 + c4) = v;
    __half2 p0 = __floats2half2_rn(v.x, v.y);
    __half2 p1 = __floats2half2_rn(v.z, v.w);
    __half2* hp = (__half2*)(g_hx + (long long)node * 128 + c4);
    hp[0] = p0;
    hp[1] = p1;
}

// ---------------- weight prep: split B = {Wl | Wr} into bf16 hi/lo ----------------
__global__ void prep_b_kernel(const float* __restrict__ W1l, const float* __restrict__ W1r,
                              const float* __restrict__ W2l, const float* __restrict__ W2r) {
    int idx = blockIdx.x * blockDim.x + threadIdx.x;   // 2*128*256 = 65536
    if (idx >= 2 * 128 * 256) return;
    int which = idx >> 15;
    int rem = idx & 32767;
    int o = rem >> 8;     // 0..127 output
    int k = rem & 255;    // 0..255
    const float* Wl = which ? W2l : W1l;
    const float* Wr = which ? W2r : W1r;
    float v = (k < 128) ? Wl[o * 128 + k] : Wr[o * 128 + (k - 128)];
    __nv_bfloat16 hi = __float2bfloat16(v);
    __nv_bfloat16 lo = __float2bfloat16(v - __bfloat162float(hi));
    (which ? g_Bhi2 : g_Bhi1)[o * 256 + k] = hi;
    (which ? g_Blo2 : g_Blo1)[o * 256 + k] = lo;
}

// ---------------- mean aggregation (fp16 input): one warp per node ----------------
__global__ void aggregate_kernel(const __half* __restrict__ hx, int n) {
    int gwarp = (blockIdx.x * blockDim.x + threadIdx.x) >> 5;
    int lane = threadIdx.x & 31;
    if (gwarp >= n) return;
    int beg = g_off[gwarp];
    int end = g_off[gwarp + 1];
    float ax = 0.f, ay = 0.f, az = 0.f, aw = 0.f;
    for (int e = beg; e < end; e++) {
        int s = __ldg(&g_csr[e]);
        // 8B per lane -> 256B per row per warp
        uint2 u = *(const uint2*)(hx + (long long)s * 128 + lane * 4);
        __half2 h0 = *(__half2*)&u.x;
        __half2 h1 = *(__half2*)&u.y;
        float2 f0 = __half22float2(h0);
        float2 f1 = __half22float2(h1);
        ax += f0.x; ay += f0.y; az += f1.x; aw += f1.y;
    }
    float inv = 1.0f / fmaxf((float)(end - beg), 1.0f);
    float4 r; r.x = ax * inv; r.y = ay * inv; r.z = az * inv; r.w = aw * inv;
    *(float4*)(g_agg + (long long)gwarp * 128 + lane * 4) = r;
}

// ---------------- split-bf16 HMMA dual GEMM + bias + relu ----------------
// out[i,o] = relu( sum_k A[i,k]*B[o,k] + bias[o] ),  A = [agg | h] (K=256),
// D = Ah*Bh + Ah*Bl + Al*Bh, fp32 accum.  Optionally emits fp16 copy of out.
#define ASTRIDE 72   // bf16 elems per smem row (64 data + 8 pad) -> conflict-free

#define SO_AH 0
#define SO_AL (128 * ASTRIDE)
#define SO_BH (2 * 128 * ASTRIDE)
#define SO_BL (3 * 128 * ASTRIDE)
#define SM_BYTES (4 * 128 * ASTRIDE * 2)

__global__ __launch_bounds__(256, 2)
void hmma_gemm_kernel(const float* __restrict__ A0,   // agg [N,128]
                      const float* __restrict__ A1,   // h   [N,128]
                      const __nv_bfloat16* __restrict__ Bhi,  // [128,256]
                      const __nv_bfloat16* __restrict__ Blo,
                      const float* __restrict__ bias,
                      float* __restrict__ out,
                      __half* __restrict__ outx,      // fp16 copy (or null)
                      int n) {
    extern __shared__ __nv_bfloat16 sm[];
    __nv_bfloat16* sAh = sm + SO_AH;
    __nv_bfloat16* sAl = sm + SO_AL;
    __nv_bfloat16* sBh = sm + SO_BH;
    __nv_bfloat16* sBl = sm + SO_BL;

    int tid = threadIdx.x;
    int wid = tid >> 5;
    int lid = tid & 31;
    int g = lid >> 2;       // group row (0..7)
    int tg = lid & 3;       // thread-in-group (k pairs)
    int rowBase = blockIdx.x * 128;
    int mrow = wid * 16;

    float acc[16][4];
#pragma unroll
    for (int t = 0; t < 16; t++)
#pragma unroll
        for (int j = 0; j < 4; j++) acc[t][j] = 0.f;

    for (int kc = 0; kc < 4; kc++) {
        const float* A = (kc < 2) ? A0 : A1;
        int kbase = (kc & 1) * 64;

        // ---- load A chunk: 128 rows x 64 fp32 -> split bf16 hi/lo ----
#pragma unroll
        for (int it = 0; it < 8; it++) {
            int idx = tid + it * 256;          // 0..2047 float4s
            int r = idx >> 4;
            int c4 = (idx & 15) * 4;
            int gr = rowBase + r;
            float4 v = make_float4(0.f, 0.f, 0.f, 0.f);
            if (gr < n) v = *(const float4*)(A + (long long)gr * 128 + kbase + c4);
            __nv_bfloat16 hx = __float2bfloat16(v.x), hy = __float2bfloat16(v.y);
            __nv_bfloat16 hz = __float2bfloat16(v.z), hw = __float2bfloat16(v.w);
            __nv_bfloat162 ph0; ph0.x = hx; ph0.y = hy;
            __nv_bfloat162 ph1; ph1.x = hz; ph1.y = hw;
            __nv_bfloat162 pl0, pl1;
            pl0.x = __float2bfloat16(v.x - __bfloat162float(hx));
            pl0.y = __float2bfloat16(v.y - __bfloat162float(hy));
            pl1.x = __float2bfloat16(v.z - __bfloat162float(hz));
            pl1.y = __float2bfloat16(v.w - __bfloat162float(hw));
            int so = r * ASTRIDE + c4;
            *(__nv_bfloat162*)(sAh + so)     = ph0;
            *(__nv_bfloat162*)(sAh + so + 2) = ph1;
            *(__nv_bfloat162*)(sAl + so)     = pl0;
            *(__nv_bfloat162*)(sAl + so + 2) = pl1;
        }
        // ---- load B chunk: 128 rows x 64 bf16 (hi and lo) ----
#pragma unroll
        for (int it = 0; it < 4; it++) {
            int idx = tid + it * 256;          // 0..1023 uint4s
            int r = idx >> 3;
            int q = idx & 7;
            uint4 vh = *(const uint4*)(Bhi + r * 256 + kc * 64 + q * 8);
            uint4 vl = *(const uint4*)(Blo + r * 256 + kc * 64 + q * 8);
            *(uint4*)(sBh + r * ASTRIDE + q * 8) = vh;
            *(uint4*)(sBl + r * ASTRIDE + q * 8) = vl;
        }
        __syncthreads();

        // ---- mma over 4 k16 steps ----
#pragma unroll
        for (int ks = 0; ks < 4; ks++) {
            int k0 = ks * 16;
            uint32_t ah[4], al[4];
            int ra = (mrow + g) * ASTRIDE + k0 + tg * 2;
            int rb = (mrow + g + 8) * ASTRIDE + k0 + tg * 2;
            ah[0] = *(const uint32_t*)(sAh + ra);
            ah[1] = *(const uint32_t*)(sAh + rb);
            ah[2] = *(const uint32_t*)(sAh + ra + 8);
            ah[3] = *(const uint32_t*)(sAh + rb + 8);
            al[0] = *(const uint32_t*)(sAl + ra);
            al[1] = *(const uint32_t*)(sAl + rb);
            al[2] = *(const uint32_t*)(sAl + ra + 8);
            al[3] = *(const uint32_t*)(sAl + rb + 8);
#pragma unroll
            for (int nt = 0; nt < 16; nt++) {
                int nb = (nt * 8 + g) * ASTRIDE + k0 + tg * 2;
                uint32_t bh[2], bl[2];
                bh[0] = *(const uint32_t*)(sBh + nb);
                bh[1] = *(const uint32_t*)(sBh + nb + 8);
                bl[0] = *(const uint32_t*)(sBl + nb);
                bl[1] = *(const uint32_t*)(sBl + nb + 8);
                mma16816(acc[nt], ah, bh);
                mma16816(acc[nt], ah, bl);
                mma16816(acc[nt], al, bh);
            }
        }
        __syncthreads();
    }

    // ---- epilogue: bias + relu, float2 stores (+ optional fp16 copy) ----
    int gr0 = rowBase + mrow + g;
    int gr1 = gr0 + 8;
#pragma unroll
    for (int nt = 0; nt < 16; nt++) {
        int col = nt * 8 + tg * 2;
        float2 bb = *(const float2*)(bias + col);
        if (gr0 < n) {
            float2 o0;
            o0.x = fmaxf(acc[nt][0] + bb.x, 0.f);
            o0.y = fmaxf(acc[nt][1] + bb.y, 0.f);
            *(float2*)(out + (long long)gr0 * 128 + col) = o0;
            if (outx) *(__half2*)(outx + (long long)gr0 * 128 + col) = __floats2half2_rn(o0.x, o0.y);
        }
        if (gr1 < n) {
            float2 o1;
            o1.x = fmaxf(acc[nt][2] + bb.x, 0.f);
            o1.y = fmaxf(acc[nt][3] + bb.y, 0.f);
            *(float2*)(out + (long long)gr1 * 128 + col) = o1;
            if (outx) *(__half2*)(outx + (long long)gr1 * 128 + col) = __floats2half2_rn(o1.x, o1.y);
        }
    }
}

// ---------------- launch ----------------
extern "C" void kernel_launch(void* const* d_in, const int* in_sizes, int n_in,
                              void* d_out, int out_size) {
    // ---- rank-based classification: emb > edge > x > 4x weights > 2x biases ----
    long long sz[32];
    int used[32];
    int m = n_in > 32 ? 32 : n_in;
    for (int i = 0; i < m; i++) { sz[i] = (long long)in_sizes[i]; used[i] = 0; }

    int iEmb = -1, iEdge = -1, iX = -1;
    for (int pass = 0; pass < 3; pass++) {
        long long best = -1; int bi = -1;
        for (int i = 0; i < m; i++)
            if (!used[i] && sz[i] > best) { best = sz[i]; bi = i; }
        used[bi] = 1;
        if (pass == 0) iEmb = bi; else if (pass == 1) iEdge = bi; else iX = bi;
    }
    long long wsz = -1;
    for (int i = 0; i < m; i++) if (!used[i] && sz[i] > wsz) wsz = sz[i];
    const float* Wlist[4] = {0, 0, 0, 0};
    const float* blist[2] = {0, 0};
    int nW = 0, nb = 0;
    for (int i = 0; i < m; i++) {
        if (used[i]) continue;
        if (sz[i] == wsz && nW < 4) Wlist[nW++] = (const float*)d_in[i];
        else if (nb < 2)            blist[nb++] = (const float*)d_in[i];
    }

    const float* emb = (const float*)d_in[iEmb];
    const int*   ei  = (const int*)d_in[iEdge];
    const int*   x   = (const int*)d_in[iX];

    int bytesMode = (sz[iEmb] > 300000000LL) ? 1 : 0;
    long long div = bytesMode ? 4 : 1;
    long long embRows = sz[iEmb] / div / 128;
    long long N_ll = (long long)out_size / (128 * div);
    if (N_ll < 1) N_ll = 1;
    if (N_ll > NN) N_ll = NN;
    int N = (int)N_ll;

    long long eiW = sz[iEdge] / div;
    long long xW  = sz[iX]   / div;
    int elemMode = bytesMode ? 0 : 1;

    long long Emax = eiW / 2; if (Emax > EE) Emax = EE; if (Emax < 1) Emax = 1;

    const float* W1l = Wlist[0];
    const float* W1r = Wlist[1];
    const float* W2l = Wlist[2];
    const float* W2r = Wlist[3];
    const float* b1  = blist[0];
    const float* b2  = blist[1];
    float* out = (float*)d_out;

    // resolve true device addresses of __device__ globals (ATS trap otherwise)
    float *p_h = nullptr, *p_h2 = nullptr, *p_agg = nullptr;
    __half *p_hx = nullptr, *p_h2x = nullptr;
    __nv_bfloat16 *p_bhi1 = nullptr, *p_blo1 = nullptr, *p_bhi2 = nullptr, *p_blo2 = nullptr;
    cudaGetSymbolAddress((void**)&p_h,    g_h);
    cudaGetSymbolAddress((void**)&p_h2,   g_h2);
    cudaGetSymbolAddress((void**)&p_agg,  g_agg);
    cudaGetSymbolAddress((void**)&p_hx,   g_hx);
    cudaGetSymbolAddress((void**)&p_h2x,  g_h2x);
    cudaGetSymbolAddress((void**)&p_bhi1, g_Bhi1);
    cudaGetSymbolAddress((void**)&p_blo1, g_Blo1);
    cudaGetSymbolAddress((void**)&p_bhi2, g_Bhi2);
    cudaGetSymbolAddress((void**)&p_blo2, g_Blo2);

    cudaFuncSetAttribute(hmma_gemm_kernel,
                         cudaFuncAttributeMaxDynamicSharedMemorySize, SM_BYTES);

    int nBlk = (N + 255) / 256;

    // ---- pipeline ----
    detect_kernel<<<1, 32>>>(ei, eiW, x, xW, elemMode);
    zero_deg_kernel<<<nBlk, 256>>>(N);
    count_kernel<<<(int)((Emax + 255) / 256), 256>>>(ei, N);
    blocksum_kernel<<<nBlk, 256>>>(N);
    scan_bsum_kernel<<<1, 256>>>(nBlk);
    write_off_kernel<<<nBlk, 256>>>(N);
    fill_kernel<<<(int)((Emax + 255) / 256), 256>>>(ei, N);

    gather_kernel<<<(N * 32 + 255) / 256, 256>>>(x, emb, N, embRows);
    prep_b_kernel<<<(65536 + 255) / 256, 256>>>(W1l, W1r, W2l, W2r);

    int aggBlocks = (N * 32 + 255) / 256;
    int gemmBlocks = (N + 127) / 128;

    aggregate_kernel<<<aggBlocks, 256>>>(p_hx, N);
    hmma_gemm_kernel<<<gemmBlocks, 256, SM_BYTES>>>(p_agg, p_h, p_bhi1, p_blo1, b1, p_h2, p_h2x, N);

    aggregate_kernel<<<aggBlocks, 256>>>(p_h2x, N);
    hmma_gemm_kernel<<<gemmBlocks, 256, SM_BYTES>>>(p_agg, p_h2, p_bhi2, p_blo2, b2, out, (  __half*)nullptr, N);
}

// round 10
// speedup vs baseline: 2.1772x; 1.0163x over previous
#include <cuda_runtime.h>
#include <cuda_bf16.h>
#include <cuda_fp16.h>
#include <cstdint>

#define NN 50000        // capacity: nodes
#define EE 800000       // capacity: edges
#define HID 128

// ---------------- scratch (static __device__, no allocation) ----------------
__device__ float g_h[NN * 128];
__device__ float g_h2[NN * 128];
__device__ float g_agg[NN * 128];
__device__ __half g_hx[NN * 128];    // fp16 copy of h   (aggregation input L1)
__device__ __half g_h2x[NN * 128];   // fp16 copy of h2  (aggregation input L2)
__device__ int   g_deg[NN];
__device__ int   g_off[NN];          // beg offsets (disjoint, not globally ordered)
__device__ int   g_cur[NN];
__device__ int   g_csr[EE];
__device__ __nv_bfloat16 g_Bhi1[128 * 256];   // B[o][k] = {W1_l | W1_r} hi
__device__ __nv_bfloat16 g_Blo1[128 * 256];   // residual lo
__device__ __nv_bfloat16 g_Bhi2[128 * 256];
__device__ __nv_bfloat16 g_Blo2[128 * 256];
__device__ int   g_ctr;      // global offset allocator
__device__ int   g_E;        // true edge count (device-detected)
__device__ int   g_e64;      // edge_index is int64
__device__ int   g_x64;      // x is int64

// ---------------- warp-level bf16 MMA (plain PTX, no arch-'a' gating) -------
__device__ __forceinline__ void mma16816(float* d, const uint32_t* a, const uint32_t* b) {
    asm volatile(
        "mma.sync.aligned.m16n8k16.row.col.f32.bf16.bf16.f32 "
        "{%0,%1,%2,%3}, {%4,%5,%6,%7}, {%8,%9}, {%0,%1,%2,%3};"
        : "+f"(d[0]), "+f"(d[1]), "+f"(d[2]), "+f"(d[3])
        : "r"(a[0]), "r"(a[1]), "r"(a[2]), "r"(a[3]), "r"(b[0]), "r"(b[1]));
}

// ---------------- init: zero deg + ctr, block0/thread0 does dtype detect ----
__global__ void init_kernel(const int* __restrict__ ei, long long eiW,
                            const int* __restrict__ x, long long xW,
                            int elemMode, int n) {
    int i = blockIdx.x * blockDim.x + threadIdx.x;
    if (i < n) g_deg[i] = 0;
    if (blockIdx.x == 0 && threadIdx.x == 0) {
        g_ctr = 0;
        int e64 = 1;
        for (long long j = 1; j < 256 && j < eiW; j += 2)
            if (ei[j] != 0) { e64 = 0; break; }
        int x64 = 1;
        for (long long j = 1; j < 256 && j < xW; j += 2)
            if (x[j] != 0) { x64 = 0; break; }
        long long E;
        if (elemMode) E = eiW / 2;
        else          E = e64 ? eiW / 4 : eiW / 2;
        if (E > EE) E = EE;
        if (E < 0)  E = 0;
        g_E = (int)E;
        g_e64 = e64;
        g_x64 = x64;
    }
}

__global__ void count_kernel(const int* __restrict__ ei, int n) {
    int i = blockIdx.x * blockDim.x + threadIdx.x;
    int E = g_E;
    if (i >= E) return;
    int e64 = g_e64;
    long long dstBase = e64 ? 2LL * E : (long long)E;
    int d = e64 ? ei[dstBase + 2LL * i] : ei[dstBase + i];
    d = max(0, min(d, n - 1));
    atomicAdd(&g_deg[d], 1);
}

// ---- single-kernel offset assignment: intra-block scan + atomic block base ----
// Offsets are disjoint but NOT globally ordered; consumers use end = beg + deg.
__global__ void assign_kernel(int n) {
    __shared__ int s[256];
    __shared__ int base;
    int t = threadIdx.x;
    int i = blockIdx.x * 256 + t;
    int v = (i < n) ? g_deg[i] : 0;
    s[t] = v;
    __syncthreads();
    for (int d = 1; d < 256; d <<= 1) {
        int u = (t >= d) ? s[t - d] : 0;
        __syncthreads();
        s[t] += u;
        __syncthreads();
    }
    if (t == 255) base = atomicAdd(&g_ctr, s[255]);
    __syncthreads();
    int beg = s[t] - v + base;
    if (i < n) {
        g_off[i] = beg;
        g_cur[i] = beg;
    }
}

__global__ void fill_kernel(const int* __restrict__ ei, int n) {
    int i = blockIdx.x * blockDim.x + threadIdx.x;
    int E = g_E;
    if (i >= E) return;
    int e64 = g_e64;
    long long dstBase = e64 ? 2LL * E : (long long)E;
    int sv = e64 ? ei[2LL * i] : ei[i];
    int dv = e64 ? ei[dstBase + 2LL * i] : ei[dstBase + i];
    sv = max(0, min(sv, n - 1));
    dv = max(0, min(dv, n - 1));
    int pos = atomicAdd(&g_cur[dv], 1);
    if (pos < EE) g_csr[pos] = sv;
}

// ---------------- fused embedding gather + weight split-prep ----------------
__global__ void gatherprep_kernel(const int* __restrict__ x, const float* __restrict__ emb,
                                  int n, long long embRows,
                                  const float* __restrict__ W1l, const float* __restrict__ W1r,
                                  const float* __restrict__ W2l, const float* __restrict__ W2r) {
    int idx = blockIdx.x * blockDim.x + threadIdx.x;
    int gWork = n * 32;
    if (idx < gWork) {
        int node = idx >> 5;
        int c4 = (idx & 31) * 4;
        long long row = g_x64 ? (long long)x[2LL * node] : (long long)x[node];
        if (row < 0) row = 0;
        if (row >= embRows) row = embRows - 1;
        float4 v = *(const float4*)(emb + row * 128 + c4);
        *(float4*)(g_h + (long long)node * 128 + c4) = v;
        __half2 p0 = __floats2half2_rn(v.x, v.y);
        __half2 p1 = __floats2half2_rn(v.z, v.w);
        __half2* hp = (__half2*)(g_hx + (long long)node * 128 + c4);
        hp[0] = p0;
        hp[1] = p1;
    } else {
        int w = idx - gWork;              // 0 .. 2*128*256-1
        if (w >= 2 * 128 * 256) return;
        int which = w >> 15;
        int rem = w & 32767;
        int o = rem >> 8;
        int k = rem & 255;
        const float* Wl = which ? W2l : W1l;
        const float* Wr = which ? W2r : W1r;
        float v = (k < 128) ? Wl[o * 128 + k] : Wr[o * 128 + (k - 128)];
        __nv_bfloat16 hi = __float2bfloat16(v);
        __nv_bfloat16 lo = __float2bfloat16(v - __bfloat162float(hi));
        (which ? g_Bhi2 : g_Bhi1)[o * 256 + k] = hi;
        (which ? g_Blo2 : g_Blo1)[o * 256 + k] = lo;
    }
}

// ---------------- mean aggregation: 2 nodes per warp, 16 lanes each ----------
__global__ void aggregate_kernel(const __half* __restrict__ hx, int n) {
    int warp = (blockIdx.x * blockDim.x + threadIdx.x) >> 5;
    int lane = threadIdx.x & 31;
    int node = warp * 2 + (lane >> 4);
    int sub = lane & 15;                  // 16 lanes x 16B = 256B row
    if (node >= n) return;
    int beg = g_off[node];
    int deg = g_deg[node];
    float a0 = 0.f, a1 = 0.f, a2 = 0.f, a3 = 0.f;
    float a4 = 0.f, a5 = 0.f, a6 = 0.f, a7 = 0.f;
    for (int e = beg; e < beg + deg; e++) {
        int s = __ldg(&g_csr[e]);
        uint4 u = *(const uint4*)(hx + (long long)s * 128 + sub * 8);
        __half2* hp = (__half2*)&u;
        float2 f0 = __half22float2(hp[0]);
        float2 f1 = __half22float2(hp[1]);
        float2 f2 = __half22float2(hp[2]);
        float2 f3 = __half22float2(hp[3]);
        a0 += f0.x; a1 += f0.y; a2 += f1.x; a3 += f1.y;
        a4 += f2.x; a5 += f2.y; a6 += f3.x; a7 += f3.y;
    }
    float inv = 1.0f / fmaxf((float)deg, 1.0f);
    float4 r0 = make_float4(a0 * inv, a1 * inv, a2 * inv, a3 * inv);
    float4 r1 = make_float4(a4 * inv, a5 * inv, a6 * inv, a7 * inv);
    float* op = g_agg + (long long)node * 128 + sub * 8;
    *(float4*)op = r0;
    *(float4*)(op + 4) = r1;
}

// ---------------- split-bf16 HMMA dual GEMM + bias + relu ----------------
#define ASTRIDE 72   // bf16 elems per smem row (64 data + 8 pad) -> conflict-free

#define SO_AH 0
#define SO_AL (128 * ASTRIDE)
#define SO_BH (2 * 128 * ASTRIDE)
#define SO_BL (3 * 128 * ASTRIDE)
#define SM_BYTES (4 * 128 * ASTRIDE * 2)

__global__ __launch_bounds__(256, 2)
void hmma_gemm_kernel(const float* __restrict__ A0,   // agg [N,128]
                      const float* __restrict__ A1,   // h   [N,128]
                      const __nv_bfloat16* __restrict__ Bhi,  // [128,256]
                      const __nv_bfloat16* __restrict__ Blo,
                      const float* __restrict__ bias,
                      float* __restrict__ out,
                      __half* __restrict__ outx,      // fp16 copy (or null)
                      int n) {
    extern __shared__ __nv_bfloat16 sm[];
    __nv_bfloat16* sAh = sm + SO_AH;
    __nv_bfloat16* sAl = sm + SO_AL;
    __nv_bfloat16* sBh = sm + SO_BH;
    __nv_bfloat16* sBl = sm + SO_BL;

    int tid = threadIdx.x;
    int wid = tid >> 5;
    int lid = tid & 31;
    int g = lid >> 2;       // group row (0..7)
    int tg = lid & 3;       // thread-in-group (k pairs)
    int rowBase = blockIdx.x * 128;
    int mrow = wid * 16;

    float acc[16][4];
#pragma unroll
    for (int t = 0; t < 16; t++)
#pragma unroll
        for (int j = 0; j < 4; j++) acc[t][j] = 0.f;

    for (int kc = 0; kc < 4; kc++) {
        const float* A = (kc < 2) ? A0 : A1;
        int kbase = (kc & 1) * 64;

        // ---- load A chunk: 128 rows x 64 fp32 -> split bf16 hi/lo ----
#pragma unroll
        for (int it = 0; it < 8; it++) {
            int idx = tid + it * 256;          // 0..2047 float4s
            int r = idx >> 4;
            int c4 = (idx & 15) * 4;
            int gr = rowBase + r;
            float4 v = make_float4(0.f, 0.f, 0.f, 0.f);
            if (gr < n) v = *(const float4*)(A + (long long)gr * 128 + kbase + c4);
            __nv_bfloat16 hx = __float2bfloat16(v.x), hy = __float2bfloat16(v.y);
            __nv_bfloat16 hz = __float2bfloat16(v.z), hw = __float2bfloat16(v.w);
            __nv_bfloat162 ph0; ph0.x = hx; ph0.y = hy;
            __nv_bfloat162 ph1; ph1.x = hz; ph1.y = hw;
            __nv_bfloat162 pl0, pl1;
            pl0.x = __float2bfloat16(v.x - __bfloat162float(hx));
            pl0.y = __float2bfloat16(v.y - __bfloat162float(hy));
            pl1.x = __float2bfloat16(v.z - __bfloat162float(hz));
            pl1.y = __float2bfloat16(v.w - __bfloat162float(hw));
            int so = r * ASTRIDE + c4;
            *(__nv_bfloat162*)(sAh + so)     = ph0;
            *(__nv_bfloat162*)(sAh + so + 2) = ph1;
            *(__nv_bfloat162*)(sAl + so)     = pl0;
            *(__nv_bfloat162*)(sAl + so + 2) = pl1;
        }
        // ---- load B chunk: 128 rows x 64 bf16 (hi and lo) ----
#pragma unroll
        for (int it = 0; it < 4; it++) {
            int idx = tid + it * 256;          // 0..1023 uint4s
            int r = idx >> 3;
            int q = idx & 7;
            uint4 vh = *(const uint4*)(Bhi + r * 256 + kc * 64 + q * 8);
            uint4 vl = *(const uint4*)(Blo + r * 256 + kc * 64 + q * 8);
            *(uint4*)(sBh + r * ASTRIDE + q * 8) = vh;
            *(uint4*)(sBl + r * ASTRIDE + q * 8) = vl;
        }
        __syncthreads();

        // ---- mma over 4 k16 steps ----
#pragma unroll
        for (int ks = 0; ks < 4; ks++) {
            int k0 = ks * 16;
            uint32_t ah[4], al[4];
            int ra = (mrow + g) * ASTRIDE + k0 + tg * 2;
            int rb = (mrow + g + 8) * ASTRIDE + k0 + tg * 2;
            ah[0] = *(const uint32_t*)(sAh + ra);
            ah[1] = *(const uint32_t*)(sAh + rb);
            ah[2] = *(const uint32_t*)(sAh + ra + 8);
            ah[3] = *(const uint32_t*)(sAh + rb + 8);
            al[0] = *(const uint32_t*)(sAl + ra);
            al[1] = *(const uint32_t*)(sAl + rb);
            al[2] = *(const uint32_t*)(sAl + ra + 8);
            al[3] = *(const uint32_t*)(sAl + rb + 8);
#pragma unroll
            for (int nt = 0; nt < 16; nt++) {
                int nb = (nt * 8 + g) * ASTRIDE + k0 + tg * 2;
                uint32_t bh[2], bl[2];
                bh[0] = *(const uint32_t*)(sBh + nb);
                bh[1] = *(const uint32_t*)(sBh + nb + 8);
                bl[0] = *(const uint32_t*)(sBl + nb);
                bl[1] = *(const uint32_t*)(sBl + nb + 8);
                mma16816(acc[nt], ah, bh);
                mma16816(acc[nt], ah, bl);
                mma16816(acc[nt], al, bh);
            }
        }
        __syncthreads();
    }

    // ---- epilogue: bias + relu, float2 stores (+ optional fp16 copy) ----
    int gr0 = rowBase + mrow + g;
    int gr1 = gr0 + 8;
#pragma unroll
    for (int nt = 0; nt < 16; nt++) {
        int col = nt * 8 + tg * 2;
        float2 bb = *(const float2*)(bias + col);
        if (gr0 < n) {
            float2 o0;
            o0.x = fmaxf(acc[nt][0] + bb.x, 0.f);
            o0.y = fmaxf(acc[nt][1] + bb.y, 0.f);
            *(float2*)(out + (long long)gr0 * 128 + col) = o0;
            if (outx) *(__half2*)(outx + (long long)gr0 * 128 + col) = __floats2half2_rn(o0.x, o0.y);
        }
        if (gr1 < n) {
            float2 o1;
            o1.x = fmaxf(acc[nt][2] + bb.x, 0.f);
            o1.y = fmaxf(acc[nt][3] + bb.y, 0.f);
            *(float2*)(out + (long long)gr1 * 128 + col) = o1;
            if (outx) *(__half2*)(outx + (long long)gr1 * 128 + col) = __floats2half2_rn(o1.x, o1.y);
        }
    }
}

// ---------------- launch ----------------
extern "C" void kernel_launch(void* const* d_in, const int* in_sizes, int n_in,
                              void* d_out, int out_size) {
    // ---- rank-based classification: emb > edge > x > 4x weights > 2x biases ----
    long long sz[32];
    int used[32];
    int m = n_in > 32 ? 32 : n_in;
    for (int i = 0; i < m; i++) { sz[i] = (long long)in_sizes[i]; used[i] = 0; }

    int iEmb = -1, iEdge = -1, iX = -1;
    for (int pass = 0; pass < 3; pass++) {
        long long best = -1; int bi = -1;
        for (int i = 0; i < m; i++)
            if (!used[i] && sz[i] > best) { best = sz[i]; bi = i; }
        used[bi] = 1;
        if (pass == 0) iEmb = bi; else if (pass == 1) iEdge = bi; else iX = bi;
    }
    long long wsz = -1;
    for (int i = 0; i < m; i++) if (!used[i] && sz[i] > wsz) wsz = sz[i];
    const float* Wlist[4] = {0, 0, 0, 0};
    const float* blist[2] = {0, 0};
    int nW = 0, nb = 0;
    for (int i = 0; i < m; i++) {
        if (used[i]) continue;
        if (sz[i] == wsz && nW < 4) Wlist[nW++] = (const float*)d_in[i];
        else if (nb < 2)            blist[nb++] = (const float*)d_in[i];
    }

    const float* emb = (const float*)d_in[iEmb];
    const int*   ei  = (const int*)d_in[iEdge];
    const int*   x   = (const int*)d_in[iX];

    int bytesMode = (sz[iEmb] > 300000000LL) ? 1 : 0;
    long long div = bytesMode ? 4 : 1;
    long long embRows = sz[iEmb] / div / 128;
    long long N_ll = (long long)out_size / (128 * div);
    if (N_ll < 1) N_ll = 1;
    if (N_ll > NN) N_ll = NN;
    int N = (int)N_ll;

    long long eiW = sz[iEdge] / div;
    long long xW  = sz[iX]   / div;
    int elemMode = bytesMode ? 0 : 1;

    long long Emax = eiW / 2; if (Emax > EE) Emax = EE; if (Emax < 1) Emax = 1;

    const float* W1l = Wlist[0];
    const float* W1r = Wlist[1];
    const float* W2l = Wlist[2];
    const float* W2r = Wlist[3];
    const float* b1  = blist[0];
    const float* b2  = blist[1];
    float* out = (float*)d_out;

    // resolve true device addresses of __device__ globals (ATS trap otherwise)
    float *p_h = nullptr, *p_h2 = nullptr, *p_agg = nullptr;
    __half *p_hx = nullptr, *p_h2x = nullptr;
    __nv_bfloat16 *p_bhi1 = nullptr, *p_blo1 = nullptr, *p_bhi2 = nullptr, *p_blo2 = nullptr;
    cudaGetSymbolAddress((void**)&p_h,    g_h);
    cudaGetSymbolAddress((void**)&p_h2,   g_h2);
    cudaGetSymbolAddress((void**)&p_agg,  g_agg);
    cudaGetSymbolAddress((void**)&p_hx,   g_hx);
    cudaGetSymbolAddress((void**)&p_h2x,  g_h2x);
    cudaGetSymbolAddress((void**)&p_bhi1, g_Bhi1);
    cudaGetSymbolAddress((void**)&p_blo1, g_Blo1);
    cudaGetSymbolAddress((void**)&p_bhi2, g_Bhi2);
    cudaGetSymbolAddress((void**)&p_blo2, g_Blo2);

    cudaFuncSetAttribute(hmma_gemm_kernel,
                         cudaFuncAttributeMaxDynamicSharedMemorySize, SM_BYTES);

    int nBlk = (N + 255) / 256;

    // ---- pipeline (9 launches) ----
    init_kernel<<<nBlk, 256>>>(ei, eiW, x, xW, elemMode, N);
    count_kernel<<<(int)((Emax + 255) / 256), 256>>>(ei, N);
    assign_kernel<<<nBlk, 256>>>(N);
    fill_kernel<<<(int)((Emax + 255) / 256), 256>>>(ei, N);

    int gpWork = N * 32 + 2 * 128 * 256;
    gatherprep_kernel<<<(gpWork + 255) / 256, 256>>>(x, emb, N, embRows, W1l, W1r, W2l, W2r);

    int aggBlocks = (N * 16 + 255) / 256;
    int gemmBlocks = (N + 127) / 128;

    aggregate_kernel<<<aggBlocks, 256>>>(p_hx, N);
    hmma_gemm_kernel<<<gemmBlocks, 256, SM_BYTES>>>(p_agg, p_h, p_bhi1, p_blo1, b1, p_h2, p_h2x, N);

    aggregate_kernel<<<aggBlocks, 256>>>(p_h2x, N);
    hmma_gemm_kernel<<<gemmBlocks, 256, SM_BYTES>>>(p_agg, p_h2, p_bhi2, p_blo2, b2, out, (__half*)nullptr, N);
}

// round 11
// speedup vs baseline: 2.3516x; 1.0801x over previous
#include <cuda_runtime.h>
#include <cuda_bf16.h>
#include <cuda_fp16.h>
#include <cstdint>

#define NN 50000        // capacity: nodes
#define EE 800000       // capacity: edges
#define HID 128
#define MAXDEG 96       // bucket capacity; P(deg>96) < 1e-30 for this graph

// ---------------- scratch (static __device__, no allocation) ----------------
__device__ float g_h[NN * 128];
__device__ float g_h2[NN * 128];
__device__ float g_agg[NN * 128];
__device__ __half g_hx[NN * 128];    // fp16 copy of h   (aggregation input L1)
__device__ __half g_h2x[NN * 128];   // fp16 copy of h2  (aggregation input L2)
__device__ int   g_cnt[NN];          // per-node edge count
__device__ int   g_csr2[NN * MAXDEG];
__device__ __nv_bfloat16 g_Bhi1[128 * 256];   // B[o][k] = {W1_l | W1_r} hi
__device__ __nv_bfloat16 g_Blo1[128 * 256];   // residual lo
__device__ __nv_bfloat16 g_Bhi2[128 * 256];
__device__ __nv_bfloat16 g_Blo2[128 * 256];
__device__ int   g_E;        // true edge count (device-detected)
__device__ int   g_e64;      // edge_index is int64
__device__ int   g_x64;      // x is int64

// ---------------- warp-level bf16 MMA (plain PTX, no arch-'a' gating) -------
__device__ __forceinline__ void mma16816(float* d, const uint32_t* a, const uint32_t* b) {
    asm volatile(
        "mma.sync.aligned.m16n8k16.row.col.f32.bf16.bf16.f32 "
        "{%0,%1,%2,%3}, {%4,%5,%6,%7}, {%8,%9}, {%0,%1,%2,%3};"
        : "+f"(d[0]), "+f"(d[1]), "+f"(d[2]), "+f"(d[3])
        : "r"(a[0]), "r"(a[1]), "r"(a[2]), "r"(a[3]), "r"(b[0]), "r"(b[1]));
}

// ---------------- init: zero cnt, thread0 does dtype/count detect ----------
__global__ void init_kernel(const int* __restrict__ ei, long long eiW,
                            const int* __restrict__ x, long long xW,
                            int elemMode, int n) {
    int i = blockIdx.x * blockDim.x + threadIdx.x;
    if (i < n) g_cnt[i] = 0;
    if (blockIdx.x == 0 && threadIdx.x == 0) {
        int e64 = 1;
        for (long long j = 1; j < 256 && j < eiW; j += 2)
            if (ei[j] != 0) { e64 = 0; break; }
        int x64 = 1;
        for (long long j = 1; j < 256 && j < xW; j += 2)
            if (x[j] != 0) { x64 = 0; break; }
        long long E;
        if (elemMode) E = eiW / 2;
        else          E = e64 ? eiW / 4 : eiW / 2;
        if (E > EE) E = EE;
        if (E < 0)  E = 0;
        g_E = (int)E;
        g_e64 = e64;
        g_x64 = x64;
    }
}

// ---------------- fused build: single-pass bucket CSR + gather + weight prep
__global__ void build_kernel(const int* __restrict__ ei,
                             const int* __restrict__ x, const float* __restrict__ emb,
                             int n, long long embRows,
                             const float* __restrict__ W1l, const float* __restrict__ W1r,
                             const float* __restrict__ W2l, const float* __restrict__ W2r,
                             int edgeBlocks) {
    if (blockIdx.x < edgeBlocks) {
        // ---- edge bucketing: one atomic per edge ----
        int i = blockIdx.x * blockDim.x + threadIdx.x;
        int E = g_E;
        if (i >= E) return;
        int e64 = g_e64;
        long long dstBase = e64 ? 2LL * E : (long long)E;
        int sv = e64 ? ei[2LL * i] : ei[i];
        int dv = e64 ? ei[dstBase + 2LL * i] : ei[dstBase + i];
        sv = max(0, min(sv, n - 1));
        dv = max(0, min(dv, n - 1));
        int pos = atomicAdd(&g_cnt[dv], 1);
        if (pos < MAXDEG) g_csr2[dv * MAXDEG + pos] = sv;
        // overflow (never for this input): aggregate falls back to full scan
    } else {
        int idx = (blockIdx.x - edgeBlocks) * blockDim.x + threadIdx.x;
        int gWork = n * 32;
        if (idx < gWork) {
            // ---- embedding gather: fp32 + fp16 copies ----
            int node = idx >> 5;
            int c4 = (idx & 31) * 4;
            long long row = g_x64 ? (long long)x[2LL * node] : (long long)x[node];
            if (row < 0) row = 0;
            if (row >= embRows) row = embRows - 1;
            float4 v = *(const float4*)(emb + row * 128 + c4);
            *(float4*)(g_h + (long long)node * 128 + c4) = v;
            __half2 p0 = __floats2half2_rn(v.x, v.y);
            __half2 p1 = __floats2half2_rn(v.z, v.w);
            __half2* hp = (__half2*)(g_hx + (long long)node * 128 + c4);
            hp[0] = p0;
            hp[1] = p1;
        } else {
            // ---- weight split-prep ----
            int w = idx - gWork;
            if (w >= 2 * 128 * 256) return;
            int which = w >> 15;
            int rem = w & 32767;
            int o = rem >> 8;
            int k = rem & 255;
            const float* Wl = which ? W2l : W1l;
            const float* Wr = which ? W2r : W1r;
            float v = (k < 128) ? Wl[o * 128 + k] : Wr[o * 128 + (k - 128)];
            __nv_bfloat16 hi = __float2bfloat16(v);
            __nv_bfloat16 lo = __float2bfloat16(v - __bfloat162float(hi));
            (which ? g_Bhi2 : g_Bhi1)[o * 256 + k] = hi;
            (which ? g_Blo2 : g_Blo1)[o * 256 + k] = lo;
        }
    }
}

// ---------------- mean aggregation: 2 nodes per warp, 16 lanes each ----------
__global__ void aggregate_kernel(const __half* __restrict__ hx,
                                 const int* __restrict__ ei, int n) {
    int warp = (blockIdx.x * blockDim.x + threadIdx.x) >> 5;
    int lane = threadIdx.x & 31;
    int node = warp * 2 + (lane >> 4);
    int sub = lane & 15;                  // 16 lanes x 16B = 256B row
    if (node >= n) return;
    int deg = g_cnt[node];
    float a0 = 0.f, a1 = 0.f, a2 = 0.f, a3 = 0.f;
    float a4 = 0.f, a5 = 0.f, a6 = 0.f, a7 = 0.f;
    if (deg <= MAXDEG) {
        const int* bucket = g_csr2 + node * MAXDEG;
        for (int e = 0; e < deg; e++) {
            int s = __ldg(&bucket[e]);
            uint4 u = *(const uint4*)(hx + (long long)s * 128 + sub * 8);
            __half2* hp = (__half2*)&u;
            float2 f0 = __half22float2(hp[0]);
            float2 f1 = __half22float2(hp[1]);
            float2 f2 = __half22float2(hp[2]);
            float2 f3 = __half22float2(hp[3]);
            a0 += f0.x; a1 += f0.y; a2 += f1.x; a3 += f1.y;
            a4 += f2.x; a5 += f2.y; a6 += f3.x; a7 += f3.y;
        }
    } else {
        // exact fallback: scan every edge (statistically unreachable)
        int E = g_E;
        int e64 = g_e64;
        long long dstBase = e64 ? 2LL * E : (long long)E;
        for (int i = 0; i < E; i++) {
            int dv = e64 ? ei[dstBase + 2LL * i] : ei[dstBase + i];
            if (dv != node) continue;
            int sv = e64 ? ei[2LL * i] : ei[i];
            sv = max(0, min(sv, n - 1));
            uint4 u = *(const uint4*)(hx + (long long)sv * 128 + sub * 8);
            __half2* hp = (__half2*)&u;
            float2 f0 = __half22float2(hp[0]);
            float2 f1 = __half22float2(hp[1]);
            float2 f2 = __half22float2(hp[2]);
            float2 f3 = __half22float2(hp[3]);
            a0 += f0.x; a1 += f0.y; a2 += f1.x; a3 += f1.y;
            a4 += f2.x; a5 += f2.y; a6 += f3.x; a7 += f3.y;
        }
    }
    float inv = 1.0f / fmaxf((float)deg, 1.0f);
    float4 r0 = make_float4(a0 * inv, a1 * inv, a2 * inv, a3 * inv);
    float4 r1 = make_float4(a4 * inv, a5 * inv, a6 * inv, a7 * inv);
    float* op = g_agg + (long long)node * 128 + sub * 8;
    *(float4*)op = r0;
    *(float4*)(op + 4) = r1;
}

// ---------------- split-bf16 HMMA dual GEMM + bias + relu ----------------
#define ASTRIDE 72   // bf16 elems per smem row (64 data + 8 pad) -> conflict-free

#define SO_AH 0
#define SO_AL (128 * ASTRIDE)
#define SO_BH (2 * 128 * ASTRIDE)
#define SO_BL (3 * 128 * ASTRIDE)
#define SM_BYTES (4 * 128 * ASTRIDE * 2)

__global__ __launch_bounds__(256, 2)
void hmma_gemm_kernel(const float* __restrict__ A0,   // agg [N,128]
                      const float* __restrict__ A1,   // h   [N,128]
                      const __nv_bfloat16* __restrict__ Bhi,  // [128,256]
                      const __nv_bfloat16* __restrict__ Blo,
                      const float* __restrict__ bias,
                      float* __restrict__ out,
                      __half* __restrict__ outx,      // fp16 copy (or null)
                      int n) {
    extern __shared__ __nv_bfloat16 sm[];
    __nv_bfloat16* sAh = sm + SO_AH;
    __nv_bfloat16* sAl = sm + SO_AL;
    __nv_bfloat16* sBh = sm + SO_BH;
    __nv_bfloat16* sBl = sm + SO_BL;

    int tid = threadIdx.x;
    int wid = tid >> 5;
    int lid = tid & 31;
    int g = lid >> 2;       // group row (0..7)
    int tg = lid & 3;       // thread-in-group (k pairs)
    int rowBase = blockIdx.x * 128;
    int mrow = wid * 16;

    float acc[16][4];
#pragma unroll
    for (int t = 0; t < 16; t++)
#pragma unroll
        for (int j = 0; j < 4; j++) acc[t][j] = 0.f;

    for (int kc = 0; kc < 4; kc++) {
        const float* A = (kc < 2) ? A0 : A1;
        int kbase = (kc & 1) * 64;

        // ---- load A chunk: 128 rows x 64 fp32 -> split bf16 hi/lo ----
#pragma unroll
        for (int it = 0; it < 8; it++) {
            int idx = tid + it * 256;          // 0..2047 float4s
            int r = idx >> 4;
            int c4 = (idx & 15) * 4;
            int gr = rowBase + r;
            float4 v = make_float4(0.f, 0.f, 0.f, 0.f);
            if (gr < n) v = *(const float4*)(A + (long long)gr * 128 + kbase + c4);
            __nv_bfloat16 hx = __float2bfloat16(v.x), hy = __float2bfloat16(v.y);
            __nv_bfloat16 hz = __float2bfloat16(v.z), hw = __float2bfloat16(v.w);
            __nv_bfloat162 ph0; ph0.x = hx; ph0.y = hy;
            __nv_bfloat162 ph1; ph1.x = hz; ph1.y = hw;
            __nv_bfloat162 pl0, pl1;
            pl0.x = __float2bfloat16(v.x - __bfloat162float(hx));
            pl0.y = __float2bfloat16(v.y - __bfloat162float(hy));
            pl1.x = __float2bfloat16(v.z - __bfloat162float(hz));
            pl1.y = __float2bfloat16(v.w - __bfloat162float(hw));
            int so = r * ASTRIDE + c4;
            *(__nv_bfloat162*)(sAh + so)     = ph0;
            *(__nv_bfloat162*)(sAh + so + 2) = ph1;
            *(__nv_bfloat162*)(sAl + so)     = pl0;
            *(__nv_bfloat162*)(sAl + so + 2) = pl1;
        }
        // ---- load B chunk: 128 rows x 64 bf16 (hi and lo) ----
#pragma unroll
        for (int it = 0; it < 4; it++) {
            int idx = tid + it * 256;          // 0..1023 uint4s
            int r = idx >> 3;
            int q = idx & 7;
            uint4 vh = *(const uint4*)(Bhi + r * 256 + kc * 64 + q * 8);
            uint4 vl = *(const uint4*)(Blo + r * 256 + kc * 64 + q * 8);
            *(uint4*)(sBh + r * ASTRIDE + q * 8) = vh;
            *(uint4*)(sBl + r * ASTRIDE + q * 8) = vl;
        }
        __syncthreads();

        // ---- mma over 4 k16 steps ----
#pragma unroll
        for (int ks = 0; ks < 4; ks++) {
            int k0 = ks * 16;
            uint32_t ah[4], al[4];
            int ra = (mrow + g) * ASTRIDE + k0 + tg * 2;
            int rb = (mrow + g + 8) * ASTRIDE + k0 + tg * 2;
            ah[0] = *(const uint32_t*)(sAh + ra);
            ah[1] = *(const uint32_t*)(sAh + rb);
            ah[2] = *(const uint32_t*)(sAh + ra + 8);
            ah[3] = *(const uint32_t*)(sAh + rb + 8);
            al[0] = *(const uint32_t*)(sAl + ra);
            al[1] = *(const uint32_t*)(sAl + rb);
            al[2] = *(const uint32_t*)(sAl + ra + 8);
            al[3] = *(const uint32_t*)(sAl + rb + 8);
#pragma unroll
            for (int nt = 0; nt < 16; nt++) {
                int nb = (nt * 8 + g) * ASTRIDE + k0 + tg * 2;
                uint32_t bh[2], bl[2];
                bh[0] = *(const uint32_t*)(sBh + nb);
                bh[1] = *(const uint32_t*)(sBh + nb + 8);
                bl[0] = *(const uint32_t*)(sBl + nb);
                bl[1] = *(const uint32_t*)(sBl + nb + 8);
                mma16816(acc[nt], ah, bh);
                mma16816(acc[nt], ah, bl);
                mma16816(acc[nt], al, bh);
            }
        }
        __syncthreads();
    }

    // ---- epilogue: bias + relu, float2 stores (+ optional fp16 copy) ----
    int gr0 = rowBase + mrow + g;
    int gr1 = gr0 + 8;
#pragma unroll
    for (int nt = 0; nt < 16; nt++) {
        int col = nt * 8 + tg * 2;
        float2 bb = *(const float2*)(bias + col);
        if (gr0 < n) {
            float2 o0;
            o0.x = fmaxf(acc[nt][0] + bb.x, 0.f);
            o0.y = fmaxf(acc[nt][1] + bb.y, 0.f);
            *(float2*)(out + (long long)gr0 * 128 + col) = o0;
            if (outx) *(__half2*)(outx + (long long)gr0 * 128 + col) = __floats2half2_rn(o0.x, o0.y);
        }
        if (gr1 < n) {
            float2 o1;
            o1.x = fmaxf(acc[nt][2] + bb.x, 0.f);
            o1.y = fmaxf(acc[nt][3] + bb.y, 0.f);
            *(float2*)(out + (long long)gr1 * 128 + col) = o1;
            if (outx) *(__half2*)(outx + (long long)gr1 * 128 + col) = __floats2half2_rn(o1.x, o1.y);
        }
    }
}

// ---------------- launch ----------------
extern "C" void kernel_launch(void* const* d_in, const int* in_sizes, int n_in,
                              void* d_out, int out_size) {
    // ---- rank-based classification: emb > edge > x > 4x weights > 2x biases ----
    long long sz[32];
    int used[32];
    int m = n_in > 32 ? 32 : n_in;
    for (int i = 0; i < m; i++) { sz[i] = (long long)in_sizes[i]; used[i] = 0; }

    int iEmb = -1, iEdge = -1, iX = -1;
    for (int pass = 0; pass < 3; pass++) {
        long long best = -1; int bi = -1;
        for (int i = 0; i < m; i++)
            if (!used[i] && sz[i] > best) { best = sz[i]; bi = i; }
        used[bi] = 1;
        if (pass == 0) iEmb = bi; else if (pass == 1) iEdge = bi; else iX = bi;
    }
    long long wsz = -1;
    for (int i = 0; i < m; i++) if (!used[i] && sz[i] > wsz) wsz = sz[i];
    const float* Wlist[4] = {0, 0, 0, 0};
    const float* blist[2] = {0, 0};
    int nW = 0, nb = 0;
    for (int i = 0; i < m; i++) {
        if (used[i]) continue;
        if (sz[i] == wsz && nW < 4) Wlist[nW++] = (const float*)d_in[i];
        else if (nb < 2)            blist[nb++] = (const float*)d_in[i];
    }

    const float* emb = (const float*)d_in[iEmb];
    const int*   ei  = (const int*)d_in[iEdge];
    const int*   x   = (const int*)d_in[iX];

    int bytesMode = (sz[iEmb] > 300000000LL) ? 1 : 0;
    long long div = bytesMode ? 4 : 1;
    long long embRows = sz[iEmb] / div / 128;
    long long N_ll = (long long)out_size / (128 * div);
    if (N_ll < 1) N_ll = 1;
    if (N_ll > NN) N_ll = NN;
    int N = (int)N_ll;

    long long eiW = sz[iEdge] / div;
    long long xW  = sz[iX]   / div;
    int elemMode = bytesMode ? 0 : 1;

    long long Emax = eiW / 2; if (Emax > EE) Emax = EE; if (Emax < 1) Emax = 1;

    const float* W1l = Wlist[0];
    const float* W1r = Wlist[1];
    const float* W2l = Wlist[2];
    const float* W2r = Wlist[3];
    const float* b1  = blist[0];
    const float* b2  = blist[1];
    float* out = (float*)d_out;

    // resolve true device addresses of __device__ globals (ATS trap otherwise)
    float *p_h = nullptr, *p_h2 = nullptr, *p_agg = nullptr;
    __half *p_hx = nullptr, *p_h2x = nullptr;
    __nv_bfloat16 *p_bhi1 = nullptr, *p_blo1 = nullptr, *p_bhi2 = nullptr, *p_blo2 = nullptr;
    cudaGetSymbolAddress((void**)&p_h,    g_h);
    cudaGetSymbolAddress((void**)&p_h2,   g_h2);
    cudaGetSymbolAddress((void**)&p_agg,  g_agg);
    cudaGetSymbolAddress((void**)&p_hx,   g_hx);
    cudaGetSymbolAddress((void**)&p_h2x,  g_h2x);
    cudaGetSymbolAddress((void**)&p_bhi1, g_Bhi1);
    cudaGetSymbolAddress((void**)&p_blo1, g_Blo1);
    cudaGetSymbolAddress((void**)&p_bhi2, g_Bhi2);
    cudaGetSymbolAddress((void**)&p_blo2, g_Blo2);

    cudaFuncSetAttribute(hmma_gemm_kernel,
                         cudaFuncAttributeMaxDynamicSharedMemorySize, SM_BYTES);

    int nBlk = (N + 255) / 256;
    int edgeBlocks = (int)((Emax + 255) / 256);
    int gpBlocks = (N * 32 + 2 * 128 * 256 + 255) / 256;

    // ---- pipeline (6 launches) ----
    init_kernel<<<nBlk, 256>>>(ei, eiW, x, xW, elemMode, N);
    build_kernel<<<edgeBlocks + gpBlocks, 256>>>(ei, x, emb, N, embRows,
                                                 W1l, W1r, W2l, W2r, edgeBlocks);

    int aggBlocks = (N * 16 + 255) / 256;
    int gemmBlocks = (N + 127) / 128;

    aggregate_kernel<<<aggBlocks, 256>>>(p_hx, ei, N);
    hmma_gemm_kernel<<<gemmBlocks, 256, SM_BYTES>>>(p_agg, p_h, p_bhi1, p_blo1, b1, p_h2, p_h2x, N);

    aggregate_kernel<<<aggBlocks, 256>>>(p_h2x, ei, N);
    hmma_gemm_kernel<<<gemmBlocks, 256, SM_BYTES>>>(p_agg, p_h2, p_bhi2, p_blo2, b2, out, (__half*)nullptr, N);
}

// round 12
// speedup vs baseline: 2.4485x; 1.0412x over previous
#include <cuda_runtime.h>
#include <cuda_bf16.h>
#include <cuda_fp16.h>
#include <cstdint>

#define NN 50000        // capacity: nodes
#define EE 800000       // capacity: edges
#define HID 128
#define MAXDEG 96       // bucket capacity; P(deg>96) < 1e-30 for this graph

// ---------------- scratch (static __device__, no allocation) ----------------
__device__ float g_h[NN * 128];
__device__ float g_h2[NN * 128];
__device__ float g_agg[NN * 128];
__device__ __half g_hx[NN * 128];    // fp16 copy of h   (aggregation input L1)
__device__ __half g_h2x[NN * 128];   // fp16 copy of h2  (aggregation input L2)
__device__ int   g_cnt[NN];          // per-node edge count
__device__ int   g_csr2[NN * MAXDEG];
__device__ __nv_bfloat16 g_Bhi1[128 * 256];   // B[o][k] = {W1_l | W1_r} hi
__device__ __nv_bfloat16 g_Blo1[128 * 256];   // residual lo
__device__ __nv_bfloat16 g_Bhi2[128 * 256];
__device__ __nv_bfloat16 g_Blo2[128 * 256];
__device__ int   g_E;        // true edge count (device-detected)
__device__ int   g_e64;      // edge_index is int64
__device__ int   g_x64;      // x is int64

// ---------------- warp-level bf16 MMA + ldmatrix (plain PTX) ----------------
__device__ __forceinline__ void mma16816(float* d, const uint32_t* a, const uint32_t* b) {
    asm volatile(
        "mma.sync.aligned.m16n8k16.row.col.f32.bf16.bf16.f32 "
        "{%0,%1,%2,%3}, {%4,%5,%6,%7}, {%8,%9}, {%0,%1,%2,%3};"
        : "+f"(d[0]), "+f"(d[1]), "+f"(d[2]), "+f"(d[3])
        : "r"(a[0]), "r"(a[1]), "r"(a[2]), "r"(a[3]), "r"(b[0]), "r"(b[1]));
}
__device__ __forceinline__ void ldsm4(uint32_t* r, uint32_t addr) {
    asm volatile("ldmatrix.sync.aligned.m8n8.x4.shared.b16 {%0,%1,%2,%3}, [%4];"
        : "=r"(r[0]), "=r"(r[1]), "=r"(r[2]), "=r"(r[3]) : "r"(addr));
}
__device__ __forceinline__ uint32_t smem_u32(const void* p) {
    uint32_t a;
    asm("{ .reg .u64 t; cvta.to.shared.u64 t, %1; cvt.u32.u64 %0, t; }" : "=r"(a) : "l"(p));
    return a;
}

// ---------------- init: zero cnt, thread0 does dtype/count detect ----------
__global__ void init_kernel(const int* __restrict__ ei, long long eiW,
                            const int* __restrict__ x, long long xW,
                            int elemMode, int n) {
    int i = blockIdx.x * blockDim.x + threadIdx.x;
    if (i < n) g_cnt[i] = 0;
    if (blockIdx.x == 0 && threadIdx.x == 0) {
        int e64 = 1;
        for (long long j = 1; j < 256 && j < eiW; j += 2)
            if (ei[j] != 0) { e64 = 0; break; }
        int x64 = 1;
        for (long long j = 1; j < 256 && j < xW; j += 2)
            if (x[j] != 0) { x64 = 0; break; }
        long long E;
        if (elemMode) E = eiW / 2;
        else          E = e64 ? eiW / 4 : eiW / 2;
        if (E > EE) E = EE;
        if (E < 0)  E = 0;
        g_E = (int)E;
        g_e64 = e64;
        g_x64 = x64;
    }
}

// ---------------- fused build: single-pass bucket CSR + gather + weight prep
__global__ void build_kernel(const int* __restrict__ ei,
                             const int* __restrict__ x, const float* __restrict__ emb,
                             int n, long long embRows,
                             const float* __restrict__ W1l, const float* __restrict__ W1r,
                             const float* __restrict__ W2l, const float* __restrict__ W2r,
                             int edgeBlocks) {
    if (blockIdx.x < edgeBlocks) {
        int i = blockIdx.x * blockDim.x + threadIdx.x;
        int E = g_E;
        if (i >= E) return;
        int e64 = g_e64;
        long long dstBase = e64 ? 2LL * E : (long long)E;
        int sv = e64 ? ei[2LL * i] : ei[i];
        int dv = e64 ? ei[dstBase + 2LL * i] : ei[dstBase + i];
        sv = max(0, min(sv, n - 1));
        dv = max(0, min(dv, n - 1));
        int pos = atomicAdd(&g_cnt[dv], 1);
        if (pos < MAXDEG) g_csr2[dv * MAXDEG + pos] = sv;
    } else {
        int idx = (blockIdx.x - edgeBlocks) * blockDim.x + threadIdx.x;
        int gWork = n * 32;
        if (idx < gWork) {
            int node = idx >> 5;
            int c4 = (idx & 31) * 4;
            long long row = g_x64 ? (long long)x[2LL * node] : (long long)x[node];
            if (row < 0) row = 0;
            if (row >= embRows) row = embRows - 1;
            float4 v = *(const float4*)(emb + row * 128 + c4);
            *(float4*)(g_h + (long long)node * 128 + c4) = v;
            __half2 p0 = __floats2half2_rn(v.x, v.y);
            __half2 p1 = __floats2half2_rn(v.z, v.w);
            __half2* hp = (__half2*)(g_hx + (long long)node * 128 + c4);
            hp[0] = p0;
            hp[1] = p1;
        } else {
            int w = idx - gWork;
            if (w >= 2 * 128 * 256) return;
            int which = w >> 15;
            int rem = w & 32767;
            int o = rem >> 8;
            int k = rem & 255;
            const float* Wl = which ? W2l : W1l;
            const float* Wr = which ? W2r : W1r;
            float v = (k < 128) ? Wl[o * 128 + k] : Wr[o * 128 + (k - 128)];
            __nv_bfloat16 hi = __float2bfloat16(v);
            __nv_bfloat16 lo = __float2bfloat16(v - __bfloat162float(hi));
            (which ? g_Bhi2 : g_Bhi1)[o * 256 + k] = hi;
            (which ? g_Blo2 : g_Blo1)[o * 256 + k] = lo;
        }
    }
}

// ---------------- mean aggregation: 2 nodes per warp, 16 lanes each ----------
__global__ void aggregate_kernel(const __half* __restrict__ hx,
                                 const int* __restrict__ ei, int n) {
    int warp = (blockIdx.x * blockDim.x + threadIdx.x) >> 5;
    int lane = threadIdx.x & 31;
    int node = warp * 2 + (lane >> 4);
    int sub = lane & 15;
    if (node >= n) return;
    int deg = g_cnt[node];
    float a0 = 0.f, a1 = 0.f, a2 = 0.f, a3 = 0.f;
    float a4 = 0.f, a5 = 0.f, a6 = 0.f, a7 = 0.f;
    if (deg <= MAXDEG) {
        const int* bucket = g_csr2 + node * MAXDEG;
        for (int e = 0; e < deg; e++) {
            int s = __ldg(&bucket[e]);
            uint4 u = *(const uint4*)(hx + (long long)s * 128 + sub * 8);
            __half2* hp = (__half2*)&u;
            float2 f0 = __half22float2(hp[0]);
            float2 f1 = __half22float2(hp[1]);
            float2 f2 = __half22float2(hp[2]);
            float2 f3 = __half22float2(hp[3]);
            a0 += f0.x; a1 += f0.y; a2 += f1.x; a3 += f1.y;
            a4 += f2.x; a5 += f2.y; a6 += f3.x; a7 += f3.y;
        }
    } else {
        int E = g_E;
        int e64 = g_e64;
        long long dstBase = e64 ? 2LL * E : (long long)E;
        for (int i = 0; i < E; i++) {
            int dv = e64 ? ei[dstBase + 2LL * i] : ei[dstBase + i];
            if (dv != node) continue;
            int sv = e64 ? ei[2LL * i] : ei[i];
            sv = max(0, min(sv, n - 1));
            uint4 u = *(const uint4*)(hx + (long long)sv * 128 + sub * 8);
            __half2* hp = (__half2*)&u;
            float2 f0 = __half22float2(hp[0]);
            float2 f1 = __half22float2(hp[1]);
            float2 f2 = __half22float2(hp[2]);
            float2 f3 = __half22float2(hp[3]);
            a0 += f0.x; a1 += f0.y; a2 += f1.x; a3 += f1.y;
            a4 += f2.x; a5 += f2.y; a6 += f3.x; a7 += f3.y;
        }
    }
    float inv = 1.0f / fmaxf((float)deg, 1.0f);
    float4 r0 = make_float4(a0 * inv, a1 * inv, a2 * inv, a3 * inv);
    float4 r1 = make_float4(a4 * inv, a5 * inv, a6 * inv, a7 * inv);
    float* op = g_agg + (long long)node * 128 + sub * 8;
    *(float4*)op = r0;
    *(float4*)(op + 4) = r1;
}

// ---------------- split-bf16 HMMA dual GEMM + bias + relu (ldmatrix) --------
// Block 128x128; 8 warps as 4x2: warp (wm,wn) owns rows wm*32..+31, cols wn*64..+63.
// Per warp: 2 m16-tiles x 8 n8-tiles. D = Ah*Bh + Ah*Bl + Al*Bh, fp32 accum.
#define ASTRIDE 72   // bf16 elems per smem row (64 data + 8 pad): LDSM conflict-free

#define SO_AH 0
#define SO_AL (128 * ASTRIDE)
#define SO_BH (2 * 128 * ASTRIDE)
#define SO_BL (3 * 128 * ASTRIDE)
#define SM_BYTES (4 * 128 * ASTRIDE * 2)

__global__ __launch_bounds__(256, 2)
void hmma_gemm_kernel(const float* __restrict__ A0,   // agg [N,128]
                      const float* __restrict__ A1,   // h   [N,128]
                      const __nv_bfloat16* __restrict__ Bhi,  // [128,256]
                      const __nv_bfloat16* __restrict__ Blo,
                      const float* __restrict__ bias,
                      float* __restrict__ out,
                      __half* __restrict__ outx,      // fp16 copy (or null)
                      int n) {
    extern __shared__ __nv_bfloat16 sm[];
    __nv_bfloat16* sAh = sm + SO_AH;
    __nv_bfloat16* sAl = sm + SO_AL;
    __nv_bfloat16* sBh = sm + SO_BH;
    __nv_bfloat16* sBl = sm + SO_BL;
    uint32_t suAh = smem_u32(sAh);
    uint32_t suAl = smem_u32(sAl);
    uint32_t suBh = smem_u32(sBh);
    uint32_t suBl = smem_u32(sBl);

    int tid = threadIdx.x;
    int wid = tid >> 5;
    int lane = tid & 31;
    int wm = wid & 3;         // m tile (rows wm*32)
    int wn = wid >> 2;        // n half (cols wn*64)
    int g = lane >> 2;
    int tg = lane & 3;
    int rowBase = blockIdx.x * 128;
    int mrow = wm * 32;

    // ldmatrix per-lane byte offsets
    int laneRowA = (lane & 7) + ((lane >> 3) & 1) * 8;  // row within m16 tile
    int laneKA   = (lane >> 4) * 8;                     // k half
    uint32_t aOff0 = (uint32_t)(((mrow + laneRowA) * ASTRIDE + laneKA) * 2);
    uint32_t aOff1 = (uint32_t)(((mrow + 16 + laneRowA) * ASTRIDE + laneKA) * 2);
    int laneRowB = (lane & 7) + (lane >> 4) * 8;        // row within n16 pair
    int laneKB   = ((lane >> 3) & 1) * 8;
    uint32_t bOff[4];
#pragma unroll
    for (int p = 0; p < 4; p++)
        bOff[p] = (uint32_t)(((wn * 64 + p * 16 + laneRowB) * ASTRIDE + laneKB) * 2);

    float acc[2][8][4];
#pragma unroll
    for (int mt = 0; mt < 2; mt++)
#pragma unroll
        for (int nt = 0; nt < 8; nt++)
#pragma unroll
            for (int j = 0; j < 4; j++) acc[mt][nt][j] = 0.f;

    for (int kc = 0; kc < 4; kc++) {
        const float* A = (kc < 2) ? A0 : A1;
        int kbase = (kc & 1) * 64;

        // ---- load A chunk: 128 rows x 64 fp32 -> split bf16 hi/lo ----
#pragma unroll
        for (int it = 0; it < 8; it++) {
            int idx = tid + it * 256;          // 0..2047 float4s
            int r = idx >> 4;
            int c4 = (idx & 15) * 4;
            int gr = rowBase + r;
            float4 v = make_float4(0.f, 0.f, 0.f, 0.f);
            if (gr < n) v = *(const float4*)(A + (long long)gr * 128 + kbase + c4);
            __nv_bfloat16 hx = __float2bfloat16(v.x), hy = __float2bfloat16(v.y);
            __nv_bfloat16 hz = __float2bfloat16(v.z), hw = __float2bfloat16(v.w);
            __nv_bfloat162 ph0; ph0.x = hx; ph0.y = hy;
            __nv_bfloat162 ph1; ph1.x = hz; ph1.y = hw;
            __nv_bfloat162 pl0, pl1;
            pl0.x = __float2bfloat16(v.x - __bfloat162float(hx));
            pl0.y = __float2bfloat16(v.y - __bfloat162float(hy));
            pl1.x = __float2bfloat16(v.z - __bfloat162float(hz));
            pl1.y = __float2bfloat16(v.w - __bfloat162float(hw));
            int so = r * ASTRIDE + c4;
            *(__nv_bfloat162*)(sAh + so)     = ph0;
            *(__nv_bfloat162*)(sAh + so + 2) = ph1;
            *(__nv_bfloat162*)(sAl + so)     = pl0;
            *(__nv_bfloat162*)(sAl + so + 2) = pl1;
        }
        // ---- load B chunk: 128 rows x 64 bf16 (hi and lo) ----
#pragma unroll
        for (int it = 0; it < 4; it++) {
            int idx = tid + it * 256;          // 0..1023 uint4s
            int r = idx >> 3;
            int q = idx & 7;
            uint4 vh = *(const uint4*)(Bhi + r * 256 + kc * 64 + q * 8);
            uint4 vl = *(const uint4*)(Blo + r * 256 + kc * 64 + q * 8);
            *(uint4*)(sBh + r * ASTRIDE + q * 8) = vh;
            *(uint4*)(sBl + r * ASTRIDE + q * 8) = vl;
        }
        __syncthreads();

        // ---- mma over 4 k16 steps, ldmatrix fragment loads ----
#pragma unroll
        for (int ks = 0; ks < 4; ks++) {
            uint32_t kb = (uint32_t)(ks * 32);     // k0*2 bytes
            uint32_t ah[2][4], al[2][4];
            ldsm4(ah[0], suAh + aOff0 + kb);
            ldsm4(ah[1], suAh + aOff1 + kb);
            ldsm4(al[0], suAl + aOff0 + kb);
            ldsm4(al[1], suAl + aOff1 + kb);
#pragma unroll
            for (int p = 0; p < 4; p++) {
                uint32_t bh[4], bl[4];
                ldsm4(bh, suBh + bOff[p] + kb);
                ldsm4(bl, suBl + bOff[p] + kb);
#pragma unroll
                for (int mt = 0; mt < 2; mt++) {
                    mma16816(acc[mt][2 * p],     ah[mt], bh);
                    mma16816(acc[mt][2 * p],     ah[mt], bl);
                    mma16816(acc[mt][2 * p],     al[mt], bh);
                    mma16816(acc[mt][2 * p + 1], ah[mt], bh + 2);
                    mma16816(acc[mt][2 * p + 1], ah[mt], bl + 2);
                    mma16816(acc[mt][2 * p + 1], al[mt], bh + 2);
                }
            }
        }
        __syncthreads();
    }

    // ---- epilogue: bias + relu, float2 stores (+ optional fp16 copy) ----
#pragma unroll
    for (int mt = 0; mt < 2; mt++) {
        int gr0 = rowBase + mrow + mt * 16 + g;
        int gr1 = gr0 + 8;
#pragma unroll
        for (int nt = 0; nt < 8; nt++) {
            int col = wn * 64 + nt * 8 + tg * 2;
            float2 bb = *(const float2*)(bias + col);
            if (gr0 < n) {
                float2 o0;
                o0.x = fmaxf(acc[mt][nt][0] + bb.x, 0.f);
                o0.y = fmaxf(acc[mt][nt][1] + bb.y, 0.f);
                *(float2*)(out + (long long)gr0 * 128 + col) = o0;
                if (outx) *(__half2*)(outx + (long long)gr0 * 128 + col) = __floats2half2_rn(o0.x, o0.y);
            }
            if (gr1 < n) {
                float2 o1;
                o1.x = fmaxf(acc[mt][nt][2] + bb.x, 0.f);
                o1.y = fmaxf(acc[mt][nt][3] + bb.y, 0.f);
                *(float2*)(out + (long long)gr1 * 128 + col) = o1;
                if (outx) *(__half2*)(outx + (long long)gr1 * 128 + col) = __floats2half2_rn(o1.x, o1.y);
            }
        }
    }
}

// ---------------- launch ----------------
extern "C" void kernel_launch(void* const* d_in, const int* in_sizes, int n_in,
                              void* d_out, int out_size) {
    // ---- rank-based classification: emb > edge > x > 4x weights > 2x biases ----
    long long sz[32];
    int used[32];
    int m = n_in > 32 ? 32 : n_in;
    for (int i = 0; i < m; i++) { sz[i] = (long long)in_sizes[i]; used[i] = 0; }

    int iEmb = -1, iEdge = -1, iX = -1;
    for (int pass = 0; pass < 3; pass++) {
        long long best = -1; int bi = -1;
        for (int i = 0; i < m; i++)
            if (!used[i] && sz[i] > best) { best = sz[i]; bi = i; }
        used[bi] = 1;
        if (pass == 0) iEmb = bi; else if (pass == 1) iEdge = bi; else iX = bi;
    }
    long long wsz = -1;
    for (int i = 0; i < m; i++) if (!used[i] && sz[i] > wsz) wsz = sz[i];
    const float* Wlist[4] = {0, 0, 0, 0};
    const float* blist[2] = {0, 0};
    int nW = 0, nb = 0;
    for (int i = 0; i < m; i++) {
        if (used[i]) continue;
        if (sz[i] == wsz && nW < 4) Wlist[nW++] = (const float*)d_in[i];
        else if (nb < 2)            blist[nb++] = (const float*)d_in[i];
    }

    const float* emb = (const float*)d_in[iEmb];
    const int*   ei  = (const int*)d_in[iEdge];
    const int*   x   = (const int*)d_in[iX];

    int bytesMode = (sz[iEmb] > 300000000LL) ? 1 : 0;
    long long div = bytesMode ? 4 : 1;
    long long embRows = sz[iEmb] / div / 128;
    long long N_ll = (long long)out_size / (128 * div);
    if (N_ll < 1) N_ll = 1;
    if (N_ll > NN) N_ll = NN;
    int N = (int)N_ll;

    long long eiW = sz[iEdge] / div;
    long long xW  = sz[iX]   / div;
    int elemMode = bytesMode ? 0 : 1;

    long long Emax = eiW / 2; if (Emax > EE) Emax = EE; if (Emax < 1) Emax = 1;

    const float* W1l = Wlist[0];
    const float* W1r = Wlist[1];
    const float* W2l = Wlist[2];
    const float* W2r = Wlist[3];
    const float* b1  = blist[0];
    const float* b2  = blist[1];
    float* out = (float*)d_out;

    // resolve true device addresses of __device__ globals (ATS trap otherwise)
    float *p_h = nullptr, *p_h2 = nullptr, *p_agg = nullptr;
    __half *p_hx = nullptr, *p_h2x = nullptr;
    __nv_bfloat16 *p_bhi1 = nullptr, *p_blo1 = nullptr, *p_bhi2 = nullptr, *p_blo2 = nullptr;
    cudaGetSymbolAddress((void**)&p_h,    g_h);
    cudaGetSymbolAddress((void**)&p_h2,   g_h2);
    cudaGetSymbolAddress((void**)&p_agg,  g_agg);
    cudaGetSymbolAddress((void**)&p_hx,   g_hx);
    cudaGetSymbolAddress((void**)&p_h2x,  g_h2x);
    cudaGetSymbolAddress((void**)&p_bhi1, g_Bhi1);
    cudaGetSymbolAddress((void**)&p_blo1, g_Blo1);
    cudaGetSymbolAddress((void**)&p_bhi2, g_Bhi2);
    cudaGetSymbolAddress((void**)&p_blo2, g_Blo2);

    cudaFuncSetAttribute(hmma_gemm_kernel,
                         cudaFuncAttributeMaxDynamicSharedMemorySize, SM_BYTES);

    int nBlk = (N + 255) / 256;
    int edgeBlocks = (int)((Emax + 255) / 256);
    int gpBlocks = (N * 32 + 2 * 128 * 256 + 255) / 256;

    // ---- pipeline (6 launches) ----
    init_kernel<<<nBlk, 256>>>(ei, eiW, x, xW, elemMode, N);
    build_kernel<<<edgeBlocks + gpBlocks, 256>>>(ei, x, emb, N, embRows,
                                                 W1l, W1r, W2l, W2r, edgeBlocks);

    int aggBlocks = (N * 16 + 255) / 256;
    int gemmBlocks = (N + 127) / 128;

    aggregate_kernel<<<aggBlocks, 256>>>(p_hx, ei, N);
    hmma_gemm_kernel<<<gemmBlocks, 256, SM_BYTES>>>(p_agg, p_h, p_bhi1, p_blo1, b1, p_h2, p_h2x, N);

    aggregate_kernel<<<aggBlocks, 256>>>(p_h2x, ei, N);
    hmma_gemm_kernel<<<gemmBlocks, 256, SM_BYTES>>>(p_agg, p_h2, p_bhi2, p_blo2, b2, out, (__half*)nullptr, N);
}